// round 1
// baseline (speedup 1.0000x reference)
#include <cuda_runtime.h>

// Problem constants
#define B_  2
#define T_  2048
#define D_  512
#define H_  8
#define DK_ 64
#define M_  (B_ * T_)          // 4096 rows for the projection GEMMs

// Scratch (device globals; no allocation allowed)
__device__ float g_Q[B_ * H_ * T_ * DK_];   // [b][h][t][d]
__device__ float g_K[B_ * H_ * T_ * DK_];
__device__ float g_V[B_ * H_ * T_ * DK_];
__device__ float g_O[B_ * T_ * D_];         // [b][t][h*64+d]  (concat layout)

__device__ __forceinline__ void fma4(float4& a, float s, const float4 v) {
    a.x = fmaf(s, v.x, a.x);
    a.y = fmaf(s, v.y, a.y);
    a.z = fmaf(s, v.z, a.z);
    a.w = fmaf(s, v.w, a.w);
}
__device__ __forceinline__ float dot4(const float4 a, const float4 b, float acc) {
    acc = fmaf(a.x, b.x, acc);
    acc = fmaf(a.y, b.y, acc);
    acc = fmaf(a.z, b.z, acc);
    acc = fmaf(a.w, b.w, acc);
    return acc;
}

// ---------------------------------------------------------------------------
// Tiled GEMM: Y = X @ W^T + bias.  X:[M,512], W:[512,512] (both K-contiguous).
// MODE 0: scatter into head layout [b][h][t][d] (n-tile == one head since 64|n0)
// MODE 1: flat [m][n]
// Block (16,16); 64x64 tile; k-tile 16; 4x4 per-thread microtile.
// ---------------------------------------------------------------------------
template <int MODE>
__device__ __forceinline__ void gemm_tile(const float* __restrict__ X,
                                          const float* __restrict__ W,
                                          const float* __restrict__ bias,
                                          float* __restrict__ Y) {
    __shared__ float Xs[16][68];   // k-major, padded row stride 68 (16B aligned)
    __shared__ float Ws[16][68];
    const int tx = threadIdx.x, ty = threadIdx.y;
    const int tid = ty * 16 + tx;
    const int m0 = blockIdx.x * 64;
    const int n0 = blockIdx.y * 64;

    float acc[4][4] = {};

    for (int kt = 0; kt < 512; kt += 16) {
        __syncthreads();
        #pragma unroll
        for (int i = 0; i < 4; i++) {
            const int lin = tid + 256 * i;       // 0..1023
            const int mm = lin >> 4;
            const int kk = lin & 15;
            Xs[kk][mm] = X[(size_t)(m0 + mm) * 512 + kt + kk];
            Ws[kk][mm] = W[(size_t)(n0 + mm) * 512 + kt + kk];
        }
        __syncthreads();
        #pragma unroll
        for (int kk = 0; kk < 16; kk++) {
            const float4 a = *(const float4*)&Xs[kk][ty * 4];
            const float4 b = *(const float4*)&Ws[kk][tx * 4];
            const float av[4] = {a.x, a.y, a.z, a.w};
            const float bv[4] = {b.x, b.y, b.z, b.w};
            #pragma unroll
            for (int i = 0; i < 4; i++)
                #pragma unroll
                for (int j = 0; j < 4; j++)
                    acc[i][j] = fmaf(av[i], bv[j], acc[i][j]);
        }
    }

    #pragma unroll
    for (int i = 0; i < 4; i++) {
        const int m = m0 + ty * 4 + i;
        float4 o;
        o.x = acc[i][0] + bias[n0 + tx * 4 + 0];
        o.y = acc[i][1] + bias[n0 + tx * 4 + 1];
        o.z = acc[i][2] + bias[n0 + tx * 4 + 2];
        o.w = acc[i][3] + bias[n0 + tx * 4 + 3];
        if (MODE == 0) {
            const int b = m >> 11;           // m / T_
            const int t = m & (T_ - 1);
            const int h = n0 >> 6;           // one head per 64-wide n tile
            *(float4*)&Y[(((size_t)(b * H_ + h)) * T_ + t) * DK_ + tx * 4] = o;
        } else {
            *(float4*)&Y[(size_t)m * 512 + n0 + tx * 4] = o;
        }
    }
}

__global__ __launch_bounds__(256)
void proj_kernel(const float* __restrict__ q, const float* __restrict__ k,
                 const float* __restrict__ v,
                 const float* __restrict__ Wq, const float* __restrict__ bq,
                 const float* __restrict__ Wk, const float* __restrict__ bk,
                 const float* __restrict__ Wv, const float* __restrict__ bv,
                 float* __restrict__ gQ, float* __restrict__ gK, float* __restrict__ gV) {
    const float* X;
    const float* W;
    const float* bias;
    float* Y;
    if (blockIdx.z == 0)      { X = q; W = Wq; bias = bq; Y = gQ; }
    else if (blockIdx.z == 1) { X = k; W = Wk; bias = bk; Y = gK; }
    else                      { X = v; W = Wv; bias = bv; Y = gV; }
    gemm_tile<0>(X, W, bias, Y);
}

__global__ __launch_bounds__(256)
void outproj_kernel(const float* __restrict__ X, const float* __restrict__ W,
                    const float* __restrict__ bias, float* __restrict__ Y) {
    gemm_tile<1>(X, W, bias, Y);
}

// ---------------------------------------------------------------------------
// Attention: 16 query rows per block, full score row (2048) cached in smem.
//  pass 1: raw scores into P (smem K tiles, Q broadcasts)
//  sweeps: row max -> exp + sum -> threshold (keep e > S/T, i.e. p > mean(p))
//  pass 2: out = (P_sparse @ V) / S  (split-K over two 128-thread groups)
// Dynamic smem layout (floats):
//  P      [16*2048]   = 32768
//  Qs     [16*68]     =  1088
//  Vs0    [64*68]     =  4352   (also K tile in pass 1)
//  Vs1    [64*68]     =  4352
//  Srow   [16]
//  redbuf [2*16*64]   =  2048
// total 44624 floats = 178496 bytes
// ---------------------------------------------------------------------------
#define ATTN_SMEM_FLOATS 44624
#define ATTN_SMEM_BYTES  (ATTN_SMEM_FLOATS * 4)

__global__ __launch_bounds__(256)
void attn_kernel(const float* __restrict__ Qh, const float* __restrict__ Kh,
                 const float* __restrict__ Vh, float* __restrict__ Og) {
    extern __shared__ float sm[];
    float* P      = sm;                 // 32768
    float* Qs     = sm + 32768;         // 1088
    float* Vs0    = sm + 33856;         // 4352
    float* Vs1    = sm + 38208;         // 4352
    float* Srow   = sm + 42560;         // 16
    float* redbuf = sm + 42576;         // 2048

    const int tid  = threadIdx.x;
    const int bh   = blockIdx.y;               // b*H + h
    const int row0 = blockIdx.x * 16;
    const float* Qb = Qh + ((size_t)bh * T_ + row0) * DK_;
    const float* Kb = Kh + (size_t)bh * T_ * DK_;
    const float* Vb = Vh + (size_t)bh * T_ * DK_;

    // load 16x64 Q tile
    for (int i = tid; i < 16 * 64; i += 256)
        Qs[(i >> 6) * 68 + (i & 63)] = Qb[i];

    // ---------------- pass 1: raw scores ----------------
    const int c  = tid & 63;     // key within tile
    const int rg = tid >> 6;     // 0..3 -> rows rg, rg+4, rg+8, rg+12
    float* Ks = Vs0;             // reuse V buffer for K tiles
    for (int kt = 0; kt < 32; kt++) {
        __syncthreads();
        for (int i = tid; i < 64 * 64; i += 256)
            Ks[(i >> 6) * 68 + (i & 63)] = Kb[(size_t)kt * 4096 + i];
        __syncthreads();
        float a0 = 0.f, a1 = 0.f, a2 = 0.f, a3 = 0.f;
        const float* Kc = Ks + c * 68;
        const float* Q0 = Qs + rg * 68;
        #pragma unroll
        for (int k4 = 0; k4 < 16; k4++) {
            const float4 kv = *(const float4*)(Kc + k4 * 4);
            a0 = dot4(*(const float4*)(Q0 +  0 * 68 + k4 * 4), kv, a0);
            a1 = dot4(*(const float4*)(Q0 +  4 * 68 + k4 * 4), kv, a1);
            a2 = dot4(*(const float4*)(Q0 +  8 * 68 + k4 * 4), kv, a2);
            a3 = dot4(*(const float4*)(Q0 + 12 * 68 + k4 * 4), kv, a3);
        }
        const int pc = kt * 64 + c;
        P[(rg +  0) * 2048 + pc] = a0;
        P[(rg +  4) * 2048 + pc] = a1;
        P[(rg +  8) * 2048 + pc] = a2;
        P[(rg + 12) * 2048 + pc] = a3;
    }
    __syncthreads();

    // ---------------- softmax + mean-threshold sweeps ----------------
    {
        const int w = tid >> 5, lane = tid & 31;
        #pragma unroll
        for (int rr = 0; rr < 2; rr++) {
            const int r = w * 2 + rr;
            float4* Pr = (float4*)(P + r * 2048);
            float m = -1e30f;
            for (int j = lane; j < 512; j += 32) {
                const float4 v = Pr[j];
                m = fmaxf(m, fmaxf(fmaxf(v.x, v.y), fmaxf(v.z, v.w)));
            }
            #pragma unroll
            for (int o = 16; o; o >>= 1) m = fmaxf(m, __shfl_xor_sync(0xffffffffu, m, o));
            float s = 0.f;
            for (int j = lane; j < 512; j += 32) {
                float4 v = Pr[j];
                v.x = __expf(v.x - m); v.y = __expf(v.y - m);
                v.z = __expf(v.z - m); v.w = __expf(v.w - m);
                Pr[j] = v;
                s += (v.x + v.y) + (v.z + v.w);
            }
            #pragma unroll
            for (int o = 16; o; o >>= 1) s += __shfl_xor_sync(0xffffffffu, s, o);
            const float thr = s * (1.0f / 2048.0f);   // e > S/T  <=>  p > mean(p)
            for (int j = lane; j < 512; j += 32) {
                float4 v = Pr[j];
                v.x = (v.x > thr) ? v.x : 0.f;
                v.y = (v.y > thr) ? v.y : 0.f;
                v.z = (v.z > thr) ? v.z : 0.f;
                v.w = (v.w > thr) ? v.w : 0.f;
                Pr[j] = v;
            }
            if (lane == 0) Srow[r] = s;
        }
    }
    __syncthreads();

    // ---------------- pass 2: P_sparse @ V (split-K, 2 groups) ----------------
    const int g  = tid >> 7;             // group 0/1 -> j halves
    const int t  = tid & 127;
    const int r2 = (t >> 4) * 2;         // rows r2, r2+1
    const int c4 = (t & 15) * 4;         // 4 output dims
    float4 acc0 = {0.f, 0.f, 0.f, 0.f};
    float4 acc1 = {0.f, 0.f, 0.f, 0.f};
    float* Vsg = g ? Vs1 : Vs0;

    for (int vt = 0; vt < 16; vt++) {
        const int jb = (g * 16 + vt) * 64;
        __syncthreads();
        for (int i = t; i < 64 * 64; i += 128)
            Vsg[(i >> 6) * 68 + (i & 63)] = Vb[(size_t)jb * 64 + i];
        __syncthreads();
        const float* Pr0 = P + (size_t)r2 * 2048 + jb;
        const float* Pr1 = Pr0 + 2048;
        #pragma unroll
        for (int j4 = 0; j4 < 16; j4++) {
            const float4 p0 = *(const float4*)(Pr0 + j4 * 4);
            const float4 p1 = *(const float4*)(Pr1 + j4 * 4);
            const float4 v0 = *(const float4*)(Vsg + (j4 * 4 + 0) * 68 + c4);
            const float4 v1 = *(const float4*)(Vsg + (j4 * 4 + 1) * 68 + c4);
            const float4 v2 = *(const float4*)(Vsg + (j4 * 4 + 2) * 68 + c4);
            const float4 v3 = *(const float4*)(Vsg + (j4 * 4 + 3) * 68 + c4);
            fma4(acc0, p0.x, v0); fma4(acc0, p0.y, v1);
            fma4(acc0, p0.z, v2); fma4(acc0, p0.w, v3);
            fma4(acc1, p1.x, v0); fma4(acc1, p1.y, v1);
            fma4(acc1, p1.z, v2); fma4(acc1, p1.w, v3);
        }
    }

    __syncthreads();
    {
        float* rb = redbuf + g * 1024;
        *(float4*)(rb + (r2 + 0) * 64 + c4) = acc0;
        *(float4*)(rb + (r2 + 1) * 64 + c4) = acc1;
    }
    __syncthreads();
    {
        const int r  = tid >> 4;
        const int cc = (tid & 15) * 4;
        const float4 a  = *(const float4*)(redbuf + r * 64 + cc);
        const float4 b4 = *(const float4*)(redbuf + 1024 + r * 64 + cc);
        const float inv = 1.0f / Srow[r];
        float4 o;
        o.x = (a.x + b4.x) * inv;
        o.y = (a.y + b4.y) * inv;
        o.z = (a.z + b4.z) * inv;
        o.w = (a.w + b4.w) * inv;
        const int bb = bh >> 3;          // bh / H_
        const int hh = bh & 7;
        Og[0] = Og[0];                   // no-op keeps compiler honest about Og use
        *(float4*)&Og[((size_t)(bb * T_ + row0 + r)) * D_ + hh * 64 + cc] = o;
    }
}

// ---------------------------------------------------------------------------
// Launch
// ---------------------------------------------------------------------------
extern "C" void kernel_launch(void* const* d_in, const int* in_sizes, int n_in,
                              void* d_out, int out_size) {
    const float* q  = (const float*)d_in[0];
    const float* k  = (const float*)d_in[1];
    const float* v  = (const float*)d_in[2];
    const float* Wq = (const float*)d_in[3];
    const float* bq = (const float*)d_in[4];
    const float* Wk = (const float*)d_in[5];
    const float* bk = (const float*)d_in[6];
    const float* Wv = (const float*)d_in[7];
    const float* bv = (const float*)d_in[8];
    const float* Wo = (const float*)d_in[9];
    const float* bo = (const float*)d_in[10];
    float* out = (float*)d_out;

    float *gQ, *gK, *gV, *gO;
    cudaGetSymbolAddress((void**)&gQ, g_Q);
    cudaGetSymbolAddress((void**)&gK, g_K);
    cudaGetSymbolAddress((void**)&gV, g_V);
    cudaGetSymbolAddress((void**)&gO, g_O);

    cudaFuncSetAttribute(attn_kernel, cudaFuncAttributeMaxDynamicSharedMemorySize,
                         ATTN_SMEM_BYTES);

    const dim3 gblk(16, 16);
    proj_kernel<<<dim3(64, 8, 3), gblk>>>(q, k, v, Wq, bq, Wk, bk, Wv, bv, gQ, gK, gV);
    attn_kernel<<<dim3(128, 16), 256, ATTN_SMEM_BYTES>>>(gQ, gK, gV, gO);
    outproj_kernel<<<dim3(64, 8), gblk>>>(gO, Wo, bo, out);
}

// round 3
// speedup vs baseline: 1.9058x; 1.9058x over previous
#include <cuda_runtime.h>

// Problem constants
#define B_  2
#define T_  2048
#define D_  512
#define H_  8
#define DK_ 64

// Scratch (device globals; no allocation allowed)
__device__ float g_Q[B_ * H_ * T_ * DK_];   // [b][h][t][d]
__device__ float g_K[B_ * H_ * T_ * DK_];
__device__ float g_V[B_ * H_ * T_ * DK_];
__device__ float g_O[B_ * T_ * D_];         // [b][t][h*64+d] (concat layout)

// ---------------------------------------------------------------------------
// GEMM: Y = X @ W^T + bias.  X:[M,512], W:[N,512] (K-contiguous).
// 128x128 tile, 256 threads, 8x8 microtile (rows split 4+4, cols split 4+4),
// k-chunk 16, register prefetch of next chunk.
// MODE 0: scatter into head layout [b][h][t][d];  MODE 1: flat [m][512]
// ---------------------------------------------------------------------------
template <int MODE>
__device__ __forceinline__ void gemm128(const float* __restrict__ X,
                                        const float* __restrict__ W,
                                        const float* __restrict__ bias,
                                        float* __restrict__ Y) {
    __shared__ float Xs[16 * 132];
    __shared__ float Ws[16 * 132];
    const int tid = threadIdx.x;
    const int rg = tid >> 4;        // 16 rowgroups: rows rg*4..+3 and 64+rg*4..+3
    const int cg = tid & 15;        // 16 colgroups: cols cg*4..+3 and 64+cg*4..+3
    const int m0 = blockIdx.x * 128;
    const int n0 = blockIdx.y * 128;

    // load-slot mapping: idx = tid + i*256 over 512 slots (128 mm x 4 kk4)
    const int mm0 = tid >> 2,           kk40 = tid & 3;
    const int mm1 = (tid + 256) >> 2,   kk41 = (tid + 256) & 3;

    float acc[8][8] = {};
    float4 xr0, xr1, wr0, wr1;

    // prefetch chunk 0
    xr0 = *(const float4*)&X[(size_t)(m0 + mm0) * 512 + kk40 * 4];
    xr1 = *(const float4*)&X[(size_t)(m0 + mm1) * 512 + kk41 * 4];
    wr0 = *(const float4*)&W[(size_t)(n0 + mm0) * 512 + kk40 * 4];
    wr1 = *(const float4*)&W[(size_t)(n0 + mm1) * 512 + kk41 * 4];

    for (int kt = 0; kt < 512; kt += 16) {
        __syncthreads();
        Xs[(kk40 * 4 + 0) * 132 + mm0] = xr0.x;
        Xs[(kk40 * 4 + 1) * 132 + mm0] = xr0.y;
        Xs[(kk40 * 4 + 2) * 132 + mm0] = xr0.z;
        Xs[(kk40 * 4 + 3) * 132 + mm0] = xr0.w;
        Xs[(kk41 * 4 + 0) * 132 + mm1] = xr1.x;
        Xs[(kk41 * 4 + 1) * 132 + mm1] = xr1.y;
        Xs[(kk41 * 4 + 2) * 132 + mm1] = xr1.z;
        Xs[(kk41 * 4 + 3) * 132 + mm1] = xr1.w;
        Ws[(kk40 * 4 + 0) * 132 + mm0] = wr0.x;
        Ws[(kk40 * 4 + 1) * 132 + mm0] = wr0.y;
        Ws[(kk40 * 4 + 2) * 132 + mm0] = wr0.z;
        Ws[(kk40 * 4 + 3) * 132 + mm0] = wr0.w;
        Ws[(kk41 * 4 + 0) * 132 + mm1] = wr1.x;
        Ws[(kk41 * 4 + 1) * 132 + mm1] = wr1.y;
        Ws[(kk41 * 4 + 2) * 132 + mm1] = wr1.z;
        Ws[(kk41 * 4 + 3) * 132 + mm1] = wr1.w;
        __syncthreads();

        if (kt + 16 < 512) {
            const int kn = kt + 16;
            xr0 = *(const float4*)&X[(size_t)(m0 + mm0) * 512 + kn + kk40 * 4];
            xr1 = *(const float4*)&X[(size_t)(m0 + mm1) * 512 + kn + kk41 * 4];
            wr0 = *(const float4*)&W[(size_t)(n0 + mm0) * 512 + kn + kk40 * 4];
            wr1 = *(const float4*)&W[(size_t)(n0 + mm1) * 512 + kn + kk41 * 4];
        }

        #pragma unroll
        for (int kk = 0; kk < 16; kk++) {
            const float4 a0 = *(const float4*)&Xs[kk * 132 + rg * 4];
            const float4 a1 = *(const float4*)&Xs[kk * 132 + 64 + rg * 4];
            const float4 b0 = *(const float4*)&Ws[kk * 132 + cg * 4];
            const float4 b1 = *(const float4*)&Ws[kk * 132 + 64 + cg * 4];
            const float av[8] = {a0.x, a0.y, a0.z, a0.w, a1.x, a1.y, a1.z, a1.w};
            const float bv[8] = {b0.x, b0.y, b0.z, b0.w, b1.x, b1.y, b1.z, b1.w};
            #pragma unroll
            for (int i = 0; i < 8; i++)
                #pragma unroll
                for (int j = 0; j < 8; j++)
                    acc[i][j] = fmaf(av[i], bv[j], acc[i][j]);
        }
    }

    // epilogue
    const float4 bb0 = *(const float4*)&bias[n0 + cg * 4];
    const float4 bb1 = *(const float4*)&bias[n0 + 64 + cg * 4];
    #pragma unroll
    for (int ih = 0; ih < 2; ih++) {
        #pragma unroll
        for (int i = 0; i < 4; i++) {
            const int row = ih * 64 + rg * 4 + i;
            const int m = m0 + row;
            float4 o0, o1;
            o0.x = acc[ih * 4 + i][0] + bb0.x;
            o0.y = acc[ih * 4 + i][1] + bb0.y;
            o0.z = acc[ih * 4 + i][2] + bb0.z;
            o0.w = acc[ih * 4 + i][3] + bb0.w;
            o1.x = acc[ih * 4 + i][4] + bb1.x;
            o1.y = acc[ih * 4 + i][5] + bb1.y;
            o1.z = acc[ih * 4 + i][6] + bb1.z;
            o1.w = acc[ih * 4 + i][7] + bb1.w;
            if (MODE == 0) {
                const int b = m >> 11;
                const int t = m & (T_ - 1);
                const int n0c = n0 + cg * 4;          // col half 0
                const int n1c = n0 + 64 + cg * 4;     // col half 1
                *(float4*)&Y[(((size_t)(b * H_ + (n0c >> 6))) * T_ + t) * DK_ + (n0c & 63)] = o0;
                *(float4*)&Y[(((size_t)(b * H_ + (n1c >> 6))) * T_ + t) * DK_ + (n1c & 63)] = o1;
            } else {
                *(float4*)&Y[(size_t)m * 512 + n0 + cg * 4] = o0;
                *(float4*)&Y[(size_t)m * 512 + n0 + 64 + cg * 4] = o1;
            }
        }
    }
}

__global__ __launch_bounds__(256)
void proj_kernel(const float* __restrict__ q, const float* __restrict__ k,
                 const float* __restrict__ v,
                 const float* __restrict__ Wq, const float* __restrict__ bq,
                 const float* __restrict__ Wk, const float* __restrict__ bk,
                 const float* __restrict__ Wv, const float* __restrict__ bv,
                 float* __restrict__ gQ, float* __restrict__ gK, float* __restrict__ gV) {
    const float* X; const float* W; const float* bias; float* Y;
    if (blockIdx.z == 0)      { X = q; W = Wq; bias = bq; Y = gQ; }
    else if (blockIdx.z == 1) { X = k; W = Wk; bias = bk; Y = gK; }
    else                      { X = v; W = Wv; bias = bv; Y = gV; }
    gemm128<0>(X, W, bias, Y);
}

__global__ __launch_bounds__(256)
void outproj_kernel(const float* __restrict__ X, const float* __restrict__ W,
                    const float* __restrict__ bias, float* __restrict__ Y) {
    gemm128<1>(X, W, bias, Y);
}

// ---------------------------------------------------------------------------
// Attention kernel: 16 query rows per block, 512 threads.
// Smem layout (floats):
//   P    [16][2052]  at 0        scores -> exp values
//   Ks   [8][2052]   at 32832    K chunk transposed; reused as Vs[128][68]
//                                then redbuf[16][1024]
//   Qs   [64][16]    at 49248    Q transposed
//   Srow [16]        at 50272
// total 50288 floats = 201,152 B
// ---------------------------------------------------------------------------
#define PST      2052
#define KS_OFF   (16 * 2052)
#define QS_OFF   (KS_OFF + 8 * 2052)
#define SROW_OFF (QS_OFF + 64 * 16)
#define ATTN_SMEM_FLOATS (SROW_OFF + 16)
#define ATTN_SMEM_BYTES  (ATTN_SMEM_FLOATS * 4)

__global__ __launch_bounds__(512)
void attn_kernel(const float* __restrict__ Qh, const float* __restrict__ Kh,
                 const float* __restrict__ Vh, float* __restrict__ Og) {
    extern __shared__ float sm[];
    float* P    = sm;
    float* Ks   = sm + KS_OFF;
    float* Qs   = sm + QS_OFF;
    float* Srow = sm + SROW_OFF;

    const int tid  = threadIdx.x;
    const int bh   = blockIdx.y;
    const int row0 = blockIdx.x * 16;
    const float* Qb = Qh + ((size_t)bh * T_ + row0) * DK_;
    const float* Kb = Kh + (size_t)bh * T_ * DK_;
    const float* Vb = Vh + (size_t)bh * T_ * DK_;

    // ---- load Q tile transposed: Qs[k][r] ----
    if (tid < 256) {
        const int r   = tid & 15;
        const int kk4 = tid >> 4;      // 16 groups of 4 k
        const float4 qv = *(const float4*)&Qb[(size_t)r * DK_ + kk4 * 4];
        Qs[(kk4 * 4 + 0) * 16 + r] = qv.x;
        Qs[(kk4 * 4 + 1) * 16 + r] = qv.y;
        Qs[(kk4 * 4 + 2) * 16 + r] = qv.z;
        Qs[(kk4 * 4 + 3) * 16 + r] = qv.w;
    }

    // ---------------- pass 1: raw scores, 8x8 microtile ----------------
    {
        const int rg = tid >> 8;       // 0/1 -> rows rg*8..+7
        const int cg = tid & 255;      // cols cg*4..+3 and 1024+cg*4..+3
        float acc[8][8] = {};

        for (int kc = 0; kc < 8; kc++) {
            __syncthreads();
            // load Ks[kk][t] = K[t][kc*8+kk], 4096 float4-slots / 512 threads
            #pragma unroll
            for (int i = 0; i < 8; i++) {
                const int idx = tid + i * 512;
                const int t   = idx >> 1;
                const int kk4 = idx & 1;
                const float4 kv = *(const float4*)&Kb[(size_t)t * DK_ + kc * 8 + kk4 * 4];
                Ks[(kk4 * 4 + 0) * PST + t] = kv.x;
                Ks[(kk4 * 4 + 1) * PST + t] = kv.y;
                Ks[(kk4 * 4 + 2) * PST + t] = kv.z;
                Ks[(kk4 * 4 + 3) * PST + t] = kv.w;
            }
            __syncthreads();
            #pragma unroll
            for (int kk = 0; kk < 8; kk++) {
                const int kr = kc * 8 + kk;
                const float4 qa = *(const float4*)&Qs[kr * 16 + rg * 8];
                const float4 qb = *(const float4*)&Qs[kr * 16 + rg * 8 + 4];
                const float4 ka = *(const float4*)&Ks[kk * PST + cg * 4];
                const float4 kb2 = *(const float4*)&Ks[kk * PST + 1024 + cg * 4];
                const float qv[8] = {qa.x, qa.y, qa.z, qa.w, qb.x, qb.y, qb.z, qb.w};
                const float kv[8] = {ka.x, ka.y, ka.z, ka.w, kb2.x, kb2.y, kb2.z, kb2.w};
                #pragma unroll
                for (int i = 0; i < 8; i++)
                    #pragma unroll
                    for (int j = 0; j < 8; j++)
                        acc[i][j] = fmaf(qv[i], kv[j], acc[i][j]);
            }
        }
        __syncthreads();
        #pragma unroll
        for (int i = 0; i < 8; i++) {
            const int r = rg * 8 + i;
            *(float4*)&P[r * PST + cg * 4] =
                make_float4(acc[i][0], acc[i][1], acc[i][2], acc[i][3]);
            *(float4*)&P[r * PST + 1024 + cg * 4] =
                make_float4(acc[i][4], acc[i][5], acc[i][6], acc[i][7]);
        }
    }
    __syncthreads();

    // ---------------- sweep: ONE warp per full row (16 warps, 16 rows) -------
    {
        const int w = tid >> 5, lane = tid & 31;    // w = row index 0..15
        float4* Pr = (float4*)(P + w * PST);        // 512 float4 per row
        float m = -1e30f;
        #pragma unroll 4
        for (int j = lane; j < 512; j += 32) {
            const float4 v = Pr[j];
            m = fmaxf(m, fmaxf(fmaxf(v.x, v.y), fmaxf(v.z, v.w)));
        }
        #pragma unroll
        for (int o = 16; o; o >>= 1) m = fmaxf(m, __shfl_xor_sync(0xffffffffu, m, o));
        float s = 0.f;
        #pragma unroll 4
        for (int j = lane; j < 512; j += 32) {
            float4 v = Pr[j];
            v.x = __expf(v.x - m); v.y = __expf(v.y - m);
            v.z = __expf(v.z - m); v.w = __expf(v.w - m);
            Pr[j] = v;
            s += (v.x + v.y) + (v.z + v.w);
        }
        #pragma unroll
        for (int o = 16; o; o >>= 1) s += __shfl_xor_sync(0xffffffffu, s, o);
        if (lane == 0) Srow[w] = s;
    }
    __syncthreads();

    // ---------------- pass 2: out = (P_thr @ V), warp split-K ----------------
    // warp g handles k in [vt*128 + g*8, +8); thread: 4 rows x 8 cols
    {
        const int g    = tid >> 5;
        const int lane = tid & 31;
        const int rr   = lane >> 3;       // rows rr, 4+rr, 8+rr, 12+rr
        const int cgv  = lane & 7;        // cols cgv*4..+3 and 32+cgv*4..+3
        float thr[4];
        #pragma unroll
        for (int i = 0; i < 4; i++) thr[i] = Srow[4 * i + rr] * (1.0f / 2048.0f);

        float* Vs = Ks;                   // [128][68]
        float acc[4][8] = {};

        for (int vt = 0; vt < 16; vt++) {
            __syncthreads();
            #pragma unroll
            for (int i = 0; i < 4; i++) {
                const int idx = tid + i * 512;          // 2048 slots = 128k x 16 d4
                const int kk = idx >> 4;
                const int d4 = idx & 15;
                const float4 vv =
                    *(const float4*)&Vb[((size_t)vt * 128 + kk) * DK_ + d4 * 4];
                *(float4*)&Vs[kk * 68 + d4 * 4] = vv;
            }
            __syncthreads();
            #pragma unroll
            for (int kv = 0; kv < 8; kv++) {
                const int kl = g * 8 + kv;
                const int kglob = vt * 128 + kl;
                const float4 va = *(const float4*)&Vs[kl * 68 + cgv * 4];
                const float4 vb2 = *(const float4*)&Vs[kl * 68 + 32 + cgv * 4];
                #pragma unroll
                for (int i = 0; i < 4; i++) {
                    float p = P[(4 * i + rr) * PST + kglob];
                    p = (p > thr[i]) ? p : 0.f;
                    acc[i][0] = fmaf(p, va.x, acc[i][0]);
                    acc[i][1] = fmaf(p, va.y, acc[i][1]);
                    acc[i][2] = fmaf(p, va.z, acc[i][2]);
                    acc[i][3] = fmaf(p, va.w, acc[i][3]);
                    acc[i][4] = fmaf(p, vb2.x, acc[i][4]);
                    acc[i][5] = fmaf(p, vb2.y, acc[i][5]);
                    acc[i][6] = fmaf(p, vb2.z, acc[i][6]);
                    acc[i][7] = fmaf(p, vb2.w, acc[i][7]);
                }
            }
        }

        __syncthreads();                 // done with Vs region; reuse as redbuf
        float* redbuf = Ks;              // [16][1024]
        #pragma unroll
        for (int i = 0; i < 4; i++) {
            const int r = 4 * i + rr;
            *(float4*)&redbuf[g * 1024 + r * 64 + cgv * 4] =
                make_float4(acc[i][0], acc[i][1], acc[i][2], acc[i][3]);
            *(float4*)&redbuf[g * 1024 + r * 64 + 32 + cgv * 4] =
                make_float4(acc[i][4], acc[i][5], acc[i][6], acc[i][7]);
        }
        __syncthreads();

        // final reduce: each thread sums 16 partials for 2 outputs
        {
            const int o = tid * 2;
            const int r = o >> 6;
            const int c = o & 63;
            float s0 = 0.f, s1 = 0.f;
            #pragma unroll
            for (int gg = 0; gg < 16; gg++) {
                const float2 v = *(const float2*)&redbuf[gg * 1024 + o];
                s0 += v.x; s1 += v.y;
            }
            const float inv = 1.0f / Srow[r];
            const int bb = bh >> 3;
            const int hh = bh & 7;
            float2 out;
            out.x = s0 * inv;
            out.y = s1 * inv;
            *(float2*)&Og[((size_t)(bb * T_ + row0 + r)) * D_ + hh * 64 + c] = out;
        }
    }
}

// ---------------------------------------------------------------------------
// Launch
// ---------------------------------------------------------------------------
extern "C" void kernel_launch(void* const* d_in, const int* in_sizes, int n_in,
                              void* d_out, int out_size) {
    const float* q  = (const float*)d_in[0];
    const float* k  = (const float*)d_in[1];
    const float* v  = (const float*)d_in[2];
    const float* Wq = (const float*)d_in[3];
    const float* bq = (const float*)d_in[4];
    const float* Wk = (const float*)d_in[5];
    const float* bk = (const float*)d_in[6];
    const float* Wv = (const float*)d_in[7];
    const float* bv = (const float*)d_in[8];
    const float* Wo = (const float*)d_in[9];
    const float* bo = (const float*)d_in[10];
    float* out = (float*)d_out;

    float *gQ, *gK, *gV, *gO;
    cudaGetSymbolAddress((void**)&gQ, g_Q);
    cudaGetSymbolAddress((void**)&gK, g_K);
    cudaGetSymbolAddress((void**)&gV, g_V);
    cudaGetSymbolAddress((void**)&gO, g_O);

    cudaFuncSetAttribute(attn_kernel, cudaFuncAttributeMaxDynamicSharedMemorySize,
                         ATTN_SMEM_BYTES);

    proj_kernel<<<dim3(32, 4, 3), 256>>>(q, k, v, Wq, bq, Wk, bk, Wv, bv, gQ, gK, gV);
    attn_kernel<<<dim3(128, 16), 512, ATTN_SMEM_BYTES>>>(gQ, gK, gV, gO);
    outproj_kernel<<<dim3(32, 4), 256>>>(gO, Wo, bo, out);
}

// round 4
// speedup vs baseline: 1.9073x; 1.0008x over previous
#include <cuda_runtime.h>

// Problem constants
#define B_  2
#define T_  2048
#define D_  512
#define H_  8
#define DK_ 64

// Scratch (device globals; no allocation allowed)
__device__ float g_Q[B_ * H_ * T_ * DK_];   // [b][h][t][d]
__device__ float g_K[B_ * H_ * T_ * DK_];
__device__ float g_V[B_ * H_ * T_ * DK_];
__device__ float g_O[B_ * T_ * D_];         // [b][t][h*64+d] (concat layout)

// ---------------------------------------------------------------------------
// GEMM: Y = X @ W^T + bias.  X:[M,512], W:[N,512] (K-contiguous).
// 128x128 tile, 256 threads, 8x8 microtile (rows split 4+4, cols split 4+4),
// k-chunk 16, register prefetch of next chunk.
// MODE 0: scatter into head layout [b][h][t][d];  MODE 1: flat [m][512]
// ---------------------------------------------------------------------------
template <int MODE>
__device__ __forceinline__ void gemm128(const float* __restrict__ X,
                                        const float* __restrict__ W,
                                        const float* __restrict__ bias,
                                        float* __restrict__ Y) {
    __shared__ float Xs[16 * 132];
    __shared__ float Ws[16 * 132];
    const int tid = threadIdx.x;
    const int rg = tid >> 4;        // 16 rowgroups: rows rg*4..+3 and 64+rg*4..+3
    const int cg = tid & 15;        // 16 colgroups: cols cg*4..+3 and 64+cg*4..+3
    const int m0 = blockIdx.x * 128;
    const int n0 = blockIdx.y * 128;

    // load-slot mapping: idx = tid + i*256 over 512 slots (128 mm x 4 kk4)
    const int mm0 = tid >> 2,           kk40 = tid & 3;
    const int mm1 = (tid + 256) >> 2,   kk41 = (tid + 256) & 3;

    float acc[8][8] = {};
    float4 xr0, xr1, wr0, wr1;

    // prefetch chunk 0
    xr0 = *(const float4*)&X[(size_t)(m0 + mm0) * 512 + kk40 * 4];
    xr1 = *(const float4*)&X[(size_t)(m0 + mm1) * 512 + kk41 * 4];
    wr0 = *(const float4*)&W[(size_t)(n0 + mm0) * 512 + kk40 * 4];
    wr1 = *(const float4*)&W[(size_t)(n0 + mm1) * 512 + kk41 * 4];

    for (int kt = 0; kt < 512; kt += 16) {
        __syncthreads();
        Xs[(kk40 * 4 + 0) * 132 + mm0] = xr0.x;
        Xs[(kk40 * 4 + 1) * 132 + mm0] = xr0.y;
        Xs[(kk40 * 4 + 2) * 132 + mm0] = xr0.z;
        Xs[(kk40 * 4 + 3) * 132 + mm0] = xr0.w;
        Xs[(kk41 * 4 + 0) * 132 + mm1] = xr1.x;
        Xs[(kk41 * 4 + 1) * 132 + mm1] = xr1.y;
        Xs[(kk41 * 4 + 2) * 132 + mm1] = xr1.z;
        Xs[(kk41 * 4 + 3) * 132 + mm1] = xr1.w;
        Ws[(kk40 * 4 + 0) * 132 + mm0] = wr0.x;
        Ws[(kk40 * 4 + 1) * 132 + mm0] = wr0.y;
        Ws[(kk40 * 4 + 2) * 132 + mm0] = wr0.z;
        Ws[(kk40 * 4 + 3) * 132 + mm0] = wr0.w;
        Ws[(kk41 * 4 + 0) * 132 + mm1] = wr1.x;
        Ws[(kk41 * 4 + 1) * 132 + mm1] = wr1.y;
        Ws[(kk41 * 4 + 2) * 132 + mm1] = wr1.z;
        Ws[(kk41 * 4 + 3) * 132 + mm1] = wr1.w;
        __syncthreads();

        if (kt + 16 < 512) {
            const int kn = kt + 16;
            xr0 = *(const float4*)&X[(size_t)(m0 + mm0) * 512 + kn + kk40 * 4];
            xr1 = *(const float4*)&X[(size_t)(m0 + mm1) * 512 + kn + kk41 * 4];
            wr0 = *(const float4*)&W[(size_t)(n0 + mm0) * 512 + kn + kk40 * 4];
            wr1 = *(const float4*)&W[(size_t)(n0 + mm1) * 512 + kn + kk41 * 4];
        }

        #pragma unroll
        for (int kk = 0; kk < 16; kk++) {
            const float4 a0 = *(const float4*)&Xs[kk * 132 + rg * 4];
            const float4 a1 = *(const float4*)&Xs[kk * 132 + 64 + rg * 4];
            const float4 b0 = *(const float4*)&Ws[kk * 132 + cg * 4];
            const float4 b1 = *(const float4*)&Ws[kk * 132 + 64 + cg * 4];
            const float av[8] = {a0.x, a0.y, a0.z, a0.w, a1.x, a1.y, a1.z, a1.w};
            const float bv[8] = {b0.x, b0.y, b0.z, b0.w, b1.x, b1.y, b1.z, b1.w};
            #pragma unroll
            for (int i = 0; i < 8; i++)
                #pragma unroll
                for (int j = 0; j < 8; j++)
                    acc[i][j] = fmaf(av[i], bv[j], acc[i][j]);
        }
    }

    // epilogue
    const float4 bb0 = *(const float4*)&bias[n0 + cg * 4];
    const float4 bb1 = *(const float4*)&bias[n0 + 64 + cg * 4];
    #pragma unroll
    for (int ih = 0; ih < 2; ih++) {
        #pragma unroll
        for (int i = 0; i < 4; i++) {
            const int row = ih * 64 + rg * 4 + i;
            const int m = m0 + row;
            float4 o0, o1;
            o0.x = acc[ih * 4 + i][0] + bb0.x;
            o0.y = acc[ih * 4 + i][1] + bb0.y;
            o0.z = acc[ih * 4 + i][2] + bb0.z;
            o0.w = acc[ih * 4 + i][3] + bb0.w;
            o1.x = acc[ih * 4 + i][4] + bb1.x;
            o1.y = acc[ih * 4 + i][5] + bb1.y;
            o1.z = acc[ih * 4 + i][6] + bb1.z;
            o1.w = acc[ih * 4 + i][7] + bb1.w;
            if (MODE == 0) {
                const int b = m >> 11;
                const int t = m & (T_ - 1);
                const int n0c = n0 + cg * 4;          // col half 0
                const int n1c = n0 + 64 + cg * 4;     // col half 1
                *(float4*)&Y[(((size_t)(b * H_ + (n0c >> 6))) * T_ + t) * DK_ + (n0c & 63)] = o0;
                *(float4*)&Y[(((size_t)(b * H_ + (n1c >> 6))) * T_ + t) * DK_ + (n1c & 63)] = o1;
            } else {
                *(float4*)&Y[(size_t)m * 512 + n0 + cg * 4] = o0;
                *(float4*)&Y[(size_t)m * 512 + n0 + 64 + cg * 4] = o1;
            }
        }
    }
}

__global__ __launch_bounds__(256)
void proj_kernel(const float* __restrict__ q, const float* __restrict__ k,
                 const float* __restrict__ v,
                 const float* __restrict__ Wq, const float* __restrict__ bq,
                 const float* __restrict__ Wk, const float* __restrict__ bk,
                 const float* __restrict__ Wv, const float* __restrict__ bv,
                 float* __restrict__ gQ, float* __restrict__ gK, float* __restrict__ gV) {
    const float* X; const float* W; const float* bias; float* Y;
    if (blockIdx.z == 0)      { X = q; W = Wq; bias = bq; Y = gQ; }
    else if (blockIdx.z == 1) { X = k; W = Wk; bias = bk; Y = gK; }
    else                      { X = v; W = Wv; bias = bv; Y = gV; }
    gemm128<0>(X, W, bias, Y);
}

__global__ __launch_bounds__(256)
void outproj_kernel(const float* __restrict__ X, const float* __restrict__ W,
                    const float* __restrict__ bias, float* __restrict__ Y) {
    gemm128<1>(X, W, bias, Y);
}

// ---------------------------------------------------------------------------
// Attention kernel: 16 query rows per block, 512 threads.
// Smem layout (floats):
//   P    [16][2052]  at 0        scores -> exp values
//   Ks   [8][2052]   at 32832    K chunk transposed; reused as Vs[128][68]
//                                then redbuf[16][1024]
//   Qs   [64][16]    at 49248    Q transposed
//   Srow [16]        at 50272
// total 50288 floats = 201,152 B
// ---------------------------------------------------------------------------
#define PST      2052
#define KS_OFF   (16 * 2052)
#define QS_OFF   (KS_OFF + 8 * 2052)
#define SROW_OFF (QS_OFF + 64 * 16)
#define ATTN_SMEM_FLOATS (SROW_OFF + 16)
#define ATTN_SMEM_BYTES  (ATTN_SMEM_FLOATS * 4)

__global__ __launch_bounds__(512)
void attn_kernel(const float* __restrict__ Qh, const float* __restrict__ Kh,
                 const float* __restrict__ Vh, float* __restrict__ Og) {
    extern __shared__ float sm[];
    float* P    = sm;
    float* Ks   = sm + KS_OFF;
    float* Qs   = sm + QS_OFF;
    float* Srow = sm + SROW_OFF;

    const int tid  = threadIdx.x;
    const int bh   = blockIdx.y;
    const int row0 = blockIdx.x * 16;
    const float* Qb = Qh + ((size_t)bh * T_ + row0) * DK_;
    const float* Kb = Kh + (size_t)bh * T_ * DK_;
    const float* Vb = Vh + (size_t)bh * T_ * DK_;

    // ---- load Q tile transposed: Qs[k][r] ----
    if (tid < 256) {
        const int r   = tid & 15;
        const int kk4 = tid >> 4;      // 16 groups of 4 k
        const float4 qv = *(const float4*)&Qb[(size_t)r * DK_ + kk4 * 4];
        Qs[(kk4 * 4 + 0) * 16 + r] = qv.x;
        Qs[(kk4 * 4 + 1) * 16 + r] = qv.y;
        Qs[(kk4 * 4 + 2) * 16 + r] = qv.z;
        Qs[(kk4 * 4 + 3) * 16 + r] = qv.w;
    }

    // ---------------- pass 1: raw scores, 8x8 microtile ----------------
    {
        const int rg = tid >> 8;       // 0/1 -> rows rg*8..+7
        const int cg = tid & 255;      // cols cg*4..+3 and 1024+cg*4..+3
        float acc[8][8] = {};

        for (int kc = 0; kc < 8; kc++) {
            __syncthreads();
            // load Ks[kk][t] = K[t][kc*8+kk], 4096 float4-slots / 512 threads
            #pragma unroll
            for (int i = 0; i < 8; i++) {
                const int idx = tid + i * 512;
                const int t   = idx >> 1;
                const int kk4 = idx & 1;
                const float4 kv = *(const float4*)&Kb[(size_t)t * DK_ + kc * 8 + kk4 * 4];
                Ks[(kk4 * 4 + 0) * PST + t] = kv.x;
                Ks[(kk4 * 4 + 1) * PST + t] = kv.y;
                Ks[(kk4 * 4 + 2) * PST + t] = kv.z;
                Ks[(kk4 * 4 + 3) * PST + t] = kv.w;
            }
            __syncthreads();
            #pragma unroll
            for (int kk = 0; kk < 8; kk++) {
                const int kr = kc * 8 + kk;
                const float4 qa = *(const float4*)&Qs[kr * 16 + rg * 8];
                const float4 qb = *(const float4*)&Qs[kr * 16 + rg * 8 + 4];
                const float4 ka = *(const float4*)&Ks[kk * PST + cg * 4];
                const float4 kb2 = *(const float4*)&Ks[kk * PST + 1024 + cg * 4];
                const float qv[8] = {qa.x, qa.y, qa.z, qa.w, qb.x, qb.y, qb.z, qb.w};
                const float kv[8] = {ka.x, ka.y, ka.z, ka.w, kb2.x, kb2.y, kb2.z, kb2.w};
                #pragma unroll
                for (int i = 0; i < 8; i++)
                    #pragma unroll
                    for (int j = 0; j < 8; j++)
                        acc[i][j] = fmaf(qv[i], kv[j], acc[i][j]);
            }
        }
        __syncthreads();
        #pragma unroll
        for (int i = 0; i < 8; i++) {
            const int r = rg * 8 + i;
            *(float4*)&P[r * PST + cg * 4] =
                make_float4(acc[i][0], acc[i][1], acc[i][2], acc[i][3]);
            *(float4*)&P[r * PST + 1024 + cg * 4] =
                make_float4(acc[i][4], acc[i][5], acc[i][6], acc[i][7]);
        }
    }
    __syncthreads();

    // ---------------- sweep: ONE warp per full row (16 warps, 16 rows) -------
    {
        const int w = tid >> 5, lane = tid & 31;    // w = row index 0..15
        float4* Pr = (float4*)(P + w * PST);        // 512 float4 per row
        float m = -1e30f;
        #pragma unroll 4
        for (int j = lane; j < 512; j += 32) {
            const float4 v = Pr[j];
            m = fmaxf(m, fmaxf(fmaxf(v.x, v.y), fmaxf(v.z, v.w)));
        }
        #pragma unroll
        for (int o = 16; o; o >>= 1) m = fmaxf(m, __shfl_xor_sync(0xffffffffu, m, o));
        float s = 0.f;
        #pragma unroll 4
        for (int j = lane; j < 512; j += 32) {
            float4 v = Pr[j];
            v.x = __expf(v.x - m); v.y = __expf(v.y - m);
            v.z = __expf(v.z - m); v.w = __expf(v.w - m);
            Pr[j] = v;
            s += (v.x + v.y) + (v.z + v.w);
        }
        #pragma unroll
        for (int o = 16; o; o >>= 1) s += __shfl_xor_sync(0xffffffffu, s, o);
        if (lane == 0) Srow[w] = s;
    }
    __syncthreads();

    // ---------------- pass 2: out = (P_thr @ V), warp split-K ----------------
    // warp g handles k in [vt*128 + g*8, +8); thread: 4 rows x 8 cols
    {
        const int g    = tid >> 5;
        const int lane = tid & 31;
        const int rr   = lane >> 3;       // rows rr, 4+rr, 8+rr, 12+rr
        const int cgv  = lane & 7;        // cols cgv*4..+3 and 32+cgv*4..+3
        float thr[4];
        #pragma unroll
        for (int i = 0; i < 4; i++) thr[i] = Srow[4 * i + rr] * (1.0f / 2048.0f);

        float* Vs = Ks;                   // [128][68]
        float acc[4][8] = {};

        for (int vt = 0; vt < 16; vt++) {
            __syncthreads();
            #pragma unroll
            for (int i = 0; i < 4; i++) {
                const int idx = tid + i * 512;          // 2048 slots = 128k x 16 d4
                const int kk = idx >> 4;
                const int d4 = idx & 15;
                const float4 vv =
                    *(const float4*)&Vb[((size_t)vt * 128 + kk) * DK_ + d4 * 4];
                *(float4*)&Vs[kk * 68 + d4 * 4] = vv;
            }
            __syncthreads();
            #pragma unroll
            for (int kv = 0; kv < 8; kv++) {
                const int kl = g * 8 + kv;
                const int kglob = vt * 128 + kl;
                const float4 va = *(const float4*)&Vs[kl * 68 + cgv * 4];
                const float4 vb2 = *(const float4*)&Vs[kl * 68 + 32 + cgv * 4];
                #pragma unroll
                for (int i = 0; i < 4; i++) {
                    float p = P[(4 * i + rr) * PST + kglob];
                    p = (p > thr[i]) ? p : 0.f;
                    acc[i][0] = fmaf(p, va.x, acc[i][0]);
                    acc[i][1] = fmaf(p, va.y, acc[i][1]);
                    acc[i][2] = fmaf(p, va.z, acc[i][2]);
                    acc[i][3] = fmaf(p, va.w, acc[i][3]);
                    acc[i][4] = fmaf(p, vb2.x, acc[i][4]);
                    acc[i][5] = fmaf(p, vb2.y, acc[i][5]);
                    acc[i][6] = fmaf(p, vb2.z, acc[i][6]);
                    acc[i][7] = fmaf(p, vb2.w, acc[i][7]);
                }
            }
        }

        __syncthreads();                 // done with Vs region; reuse as redbuf
        float* redbuf = Ks;              // [16][1024]
        #pragma unroll
        for (int i = 0; i < 4; i++) {
            const int r = 4 * i + rr;
            *(float4*)&redbuf[g * 1024 + r * 64 + cgv * 4] =
                make_float4(acc[i][0], acc[i][1], acc[i][2], acc[i][3]);
            *(float4*)&redbuf[g * 1024 + r * 64 + 32 + cgv * 4] =
                make_float4(acc[i][4], acc[i][5], acc[i][6], acc[i][7]);
        }
        __syncthreads();

        // final reduce: each thread sums 16 partials for 2 outputs
        {
            const int o = tid * 2;
            const int r = o >> 6;
            const int c = o & 63;
            float s0 = 0.f, s1 = 0.f;
            #pragma unroll
            for (int gg = 0; gg < 16; gg++) {
                const float2 v = *(const float2*)&redbuf[gg * 1024 + o];
                s0 += v.x; s1 += v.y;
            }
            const float inv = 1.0f / Srow[r];
            const int bb = bh >> 3;
            const int hh = bh & 7;
            float2 out;
            out.x = s0 * inv;
            out.y = s1 * inv;
            *(float2*)&Og[((size_t)(bb * T_ + row0 + r)) * D_ + hh * 64 + c] = out;
        }
    }
}

// ---------------------------------------------------------------------------
// Launch
// ---------------------------------------------------------------------------
extern "C" void kernel_launch(void* const* d_in, const int* in_sizes, int n_in,
                              void* d_out, int out_size) {
    const float* q  = (const float*)d_in[0];
    const float* k  = (const float*)d_in[1];
    const float* v  = (const float*)d_in[2];
    const float* Wq = (const float*)d_in[3];
    const float* bq = (const float*)d_in[4];
    const float* Wk = (const float*)d_in[5];
    const float* bk = (const float*)d_in[6];
    const float* Wv = (const float*)d_in[7];
    const float* bv = (const float*)d_in[8];
    const float* Wo = (const float*)d_in[9];
    const float* bo = (const float*)d_in[10];
    float* out = (float*)d_out;

    float *gQ, *gK, *gV, *gO;
    cudaGetSymbolAddress((void**)&gQ, g_Q);
    cudaGetSymbolAddress((void**)&gK, g_K);
    cudaGetSymbolAddress((void**)&gV, g_V);
    cudaGetSymbolAddress((void**)&gO, g_O);

    cudaFuncSetAttribute(attn_kernel, cudaFuncAttributeMaxDynamicSharedMemorySize,
                         ATTN_SMEM_BYTES);

    proj_kernel<<<dim3(32, 4, 3), 256>>>(q, k, v, Wq, bq, Wk, bk, Wv, bv, gQ, gK, gV);
    attn_kernel<<<dim3(128, 16), 512, ATTN_SMEM_BYTES>>>(gQ, gK, gV, gO);
    outproj_kernel<<<dim3(32, 4), 256>>>(gO, Wo, bo, out);
}

// round 6
// speedup vs baseline: 2.1802x; 1.1431x over previous
#include <cuda_runtime.h>
#include <cstdint>

#define B_  2
#define T_  2048
#define D_  512
#define H_  8
#define DK_ 64

__device__ float  g_Q  [B_ * H_ * T_ * DK_];   // [bh][t][k] tf32 hi
__device__ float  g_Qlo[B_ * H_ * T_ * DK_];   // [bh][t][k] residual
__device__ float2 g_KT [B_ * H_ * DK_ * T_];   // [bh][k][t] (hi,lo)
__device__ float  g_V  [B_ * H_ * T_ * DK_];   // [bh][t][k] rna tf32
__device__ float  g_O  [B_ * T_ * D_];

__device__ __forceinline__ float tf32_rna(float x) {
    uint32_t r;
    asm("cvt.rna.tf32.f32 %0, %1;" : "=r"(r) : "f"(x));
    return __uint_as_float(r);
}
__device__ __forceinline__ void mma_k4(float* d, float a0, float a1, float b0) {
    asm volatile(
        "mma.sync.aligned.m16n8k4.row.col.f32.tf32.tf32.f32 "
        "{%0,%1,%2,%3}, {%4,%5}, {%6}, {%0,%1,%2,%3};\n"
        : "+f"(d[0]), "+f"(d[1]), "+f"(d[2]), "+f"(d[3])
        : "r"(__float_as_uint(a0)), "r"(__float_as_uint(a1)),
          "r"(__float_as_uint(b0)));
}
__device__ __forceinline__ void mma_k8(float* d, float a0, float a1, float a2,
                                       float a3, float b0, float b1) {
    asm volatile(
        "mma.sync.aligned.m16n8k8.row.col.f32.tf32.tf32.f32 "
        "{%0,%1,%2,%3}, {%4,%5,%6,%7}, {%8,%9}, {%0,%1,%2,%3};\n"
        : "+f"(d[0]), "+f"(d[1]), "+f"(d[2]), "+f"(d[3])
        : "r"(__float_as_uint(a0)), "r"(__float_as_uint(a1)),
          "r"(__float_as_uint(a2)), "r"(__float_as_uint(a3)),
          "r"(__float_as_uint(b0)), "r"(__float_as_uint(b1)));
}

// ---------------------------------------------------------------------------
// GEMM Y = X@W^T + bias. 128x128 tile, 256 thr, 8x8 microtile, prefetch.
// Shared buffers are passed in (ONE static allocation per kernel, not per
// template instantiation).
// MODE 0: Q -> hi(Y) + lo(Ylo), head layout
// MODE 1: K -> transposed float2(hi,lo) [bh][k][t]
// MODE 2: V -> rna-rounded, head layout
// MODE 3: flat [m][512]
// ---------------------------------------------------------------------------
template <int MODE>
__device__ __forceinline__ void gemm128(const float* __restrict__ X,
                                        const float* __restrict__ W,
                                        const float* __restrict__ bias,
                                        float* __restrict__ Y,
                                        float* __restrict__ Ylo,
                                        float* __restrict__ Xs,
                                        float* __restrict__ Ws) {
    const int tid = threadIdx.x;
    const int rg = tid >> 4, cg = tid & 15;
    const int m0 = blockIdx.x * 128, n0 = blockIdx.y * 128;
    const int mm0 = tid >> 2,         kk40 = tid & 3;
    const int mm1 = (tid + 256) >> 2, kk41 = (tid + 256) & 3;

    float acc[8][8] = {};
    float4 xr0, xr1, wr0, wr1;
    xr0 = *(const float4*)&X[(size_t)(m0 + mm0) * 512 + kk40 * 4];
    xr1 = *(const float4*)&X[(size_t)(m0 + mm1) * 512 + kk41 * 4];
    wr0 = *(const float4*)&W[(size_t)(n0 + mm0) * 512 + kk40 * 4];
    wr1 = *(const float4*)&W[(size_t)(n0 + mm1) * 512 + kk41 * 4];

    for (int kt = 0; kt < 512; kt += 16) {
        __syncthreads();
        Xs[(kk40 * 4 + 0) * 132 + mm0] = xr0.x;
        Xs[(kk40 * 4 + 1) * 132 + mm0] = xr0.y;
        Xs[(kk40 * 4 + 2) * 132 + mm0] = xr0.z;
        Xs[(kk40 * 4 + 3) * 132 + mm0] = xr0.w;
        Xs[(kk41 * 4 + 0) * 132 + mm1] = xr1.x;
        Xs[(kk41 * 4 + 1) * 132 + mm1] = xr1.y;
        Xs[(kk41 * 4 + 2) * 132 + mm1] = xr1.z;
        Xs[(kk41 * 4 + 3) * 132 + mm1] = xr1.w;
        Ws[(kk40 * 4 + 0) * 132 + mm0] = wr0.x;
        Ws[(kk40 * 4 + 1) * 132 + mm0] = wr0.y;
        Ws[(kk40 * 4 + 2) * 132 + mm0] = wr0.z;
        Ws[(kk40 * 4 + 3) * 132 + mm0] = wr0.w;
        Ws[(kk41 * 4 + 0) * 132 + mm1] = wr1.x;
        Ws[(kk41 * 4 + 1) * 132 + mm1] = wr1.y;
        Ws[(kk41 * 4 + 2) * 132 + mm1] = wr1.z;
        Ws[(kk41 * 4 + 3) * 132 + mm1] = wr1.w;
        __syncthreads();
        if (kt + 16 < 512) {
            const int kn = kt + 16;
            xr0 = *(const float4*)&X[(size_t)(m0 + mm0) * 512 + kn + kk40 * 4];
            xr1 = *(const float4*)&X[(size_t)(m0 + mm1) * 512 + kn + kk41 * 4];
            wr0 = *(const float4*)&W[(size_t)(n0 + mm0) * 512 + kn + kk40 * 4];
            wr1 = *(const float4*)&W[(size_t)(n0 + mm1) * 512 + kn + kk41 * 4];
        }
        #pragma unroll
        for (int kk = 0; kk < 16; kk++) {
            const float4 a0 = *(const float4*)&Xs[kk * 132 + rg * 4];
            const float4 a1 = *(const float4*)&Xs[kk * 132 + 64 + rg * 4];
            const float4 b0 = *(const float4*)&Ws[kk * 132 + cg * 4];
            const float4 b1 = *(const float4*)&Ws[kk * 132 + 64 + cg * 4];
            const float av[8] = {a0.x, a0.y, a0.z, a0.w, a1.x, a1.y, a1.z, a1.w};
            const float bv[8] = {b0.x, b0.y, b0.z, b0.w, b1.x, b1.y, b1.z, b1.w};
            #pragma unroll
            for (int i = 0; i < 8; i++)
                #pragma unroll
                for (int j = 0; j < 8; j++)
                    acc[i][j] = fmaf(av[i], bv[j], acc[i][j]);
        }
    }

    const float4 bb0 = *(const float4*)&bias[n0 + cg * 4];
    const float4 bb1 = *(const float4*)&bias[n0 + 64 + cg * 4];
    const float bias8[8] = {bb0.x, bb0.y, bb0.z, bb0.w, bb1.x, bb1.y, bb1.z, bb1.w};
    #pragma unroll
    for (int ih = 0; ih < 2; ih++) {
        #pragma unroll
        for (int i = 0; i < 4; i++) {
            const int m = m0 + ih * 64 + rg * 4 + i;
            const int b = m >> 11;
            const int t = m & (T_ - 1);
            float o[8];
            #pragma unroll
            for (int j = 0; j < 8; j++) o[j] = acc[ih * 4 + i][j] + bias8[j];

            if (MODE == 3) {
                *(float4*)&Y[(size_t)m * 512 + n0 + cg * 4] =
                    make_float4(o[0], o[1], o[2], o[3]);
                *(float4*)&Y[(size_t)m * 512 + n0 + 64 + cg * 4] =
                    make_float4(o[4], o[5], o[6], o[7]);
            } else if (MODE == 1) {
                float2* KT = (float2*)Y;
                #pragma unroll
                for (int j = 0; j < 8; j++) {
                    const int col = n0 + (j < 4 ? 0 : 64) + cg * 4 + (j & 3);
                    const float hi = tf32_rna(o[j]);
                    KT[((size_t)((b * H_ + (col >> 6)) * DK_ + (col & 63))) * T_ + t] =
                        make_float2(hi, o[j] - hi);
                }
            } else {
                #pragma unroll
                for (int half = 0; half < 2; half++) {
                    const int col = n0 + half * 64 + cg * 4;
                    const size_t base =
                        (((size_t)(b * H_ + (col >> 6))) * T_ + t) * DK_ + (col & 63);
                    float4 h4, l4;
                    float* hp = (float*)&h4;
                    float* lp = (float*)&l4;
                    #pragma unroll
                    for (int j = 0; j < 4; j++) {
                        const float v = o[half * 4 + j];
                        hp[j] = tf32_rna(v);
                        lp[j] = v - hp[j];
                    }
                    *(float4*)&Y[base] = h4;
                    if (MODE == 0) *(float4*)&Ylo[base] = l4;
                }
            }
        }
    }
}

__global__ __launch_bounds__(256)
void proj_kernel(const float* __restrict__ q, const float* __restrict__ k,
                 const float* __restrict__ v,
                 const float* __restrict__ Wq, const float* __restrict__ bq,
                 const float* __restrict__ Wk, const float* __restrict__ bk,
                 const float* __restrict__ Wv, const float* __restrict__ bv,
                 float* __restrict__ gQ, float* __restrict__ gQlo,
                 float* __restrict__ gKT, float* __restrict__ gV) {
    __shared__ float Xs[16 * 132];
    __shared__ float Ws[16 * 132];
    if (blockIdx.z == 0)      gemm128<0>(q, Wq, bq, gQ, gQlo, Xs, Ws);
    else if (blockIdx.z == 1) gemm128<1>(k, Wk, bk, gKT, nullptr, Xs, Ws);
    else                      gemm128<2>(v, Wv, bv, gV, nullptr, Xs, Ws);
}

__global__ __launch_bounds__(256)
void outproj_kernel(const float* __restrict__ X, const float* __restrict__ W,
                    const float* __restrict__ bias, float* __restrict__ Y) {
    __shared__ float Xs[16 * 132];
    __shared__ float Ws[16 * 132];
    gemm128<3>(X, W, bias, Y, nullptr, Xs, Ws);
}

// ---------------------------------------------------------------------------
// Attention (tf32 tensor cores): 16 rows/block, 512 threads, 16 warps.
// Smem floats: P[16][2052] @0 | VS region (Vs2 f2[64][72] / redbuf[16][1024])
// @32832 | Qs2 f2[64][17] @49216 | Srow[16] @51392  => 205,632 B
// ---------------------------------------------------------------------------
#define PST      2052
#define VS_OFF   32832
#define QS_OFF   49216
#define SROW_OFF 51392
#define ATTN_SMEM_BYTES ((SROW_OFF + 16) * 4)
#define VST 72

__global__ __launch_bounds__(512)
void attn_kernel(const float* __restrict__ Qh, const float* __restrict__ Qlo,
                 const float2* __restrict__ KT, const float* __restrict__ Vh,
                 float* __restrict__ Og) {
    extern __shared__ float sm[];
    float*  P      = sm;
    float2* Vs2    = (float2*)(sm + VS_OFF);
    float*  redbuf = sm + VS_OFF;
    float2* Qs2    = (float2*)(sm + QS_OFF);   // [k][r] stride 17
    float*  Srow   = sm + SROW_OFF;

    const int tid  = threadIdx.x;
    const int w    = tid >> 5;
    const int lane = tid & 31;
    const int gid  = lane >> 2;     // 0..7
    const int tig  = lane & 3;      // 0..3
    const int bh   = blockIdx.y;
    const int row0 = blockIdx.x * 16;

    const float*  Qb  = Qh  + ((size_t)bh * T_ + row0) * DK_;
    const float*  Qlb = Qlo + ((size_t)bh * T_ + row0) * DK_;
    const float2* KTb = KT  + (size_t)bh * DK_ * T_;
    const float*  Vb  = Vh  + (size_t)bh * T_ * DK_;

    if (tid < 256) {
        const int r = tid & 15, k4 = tid >> 4;
        const float4 h4 = *(const float4*)&Qb [(size_t)r * DK_ + k4 * 4];
        const float4 l4 = *(const float4*)&Qlb[(size_t)r * DK_ + k4 * 4];
        Qs2[(k4 * 4 + 0) * 17 + r] = make_float2(h4.x, l4.x);
        Qs2[(k4 * 4 + 1) * 17 + r] = make_float2(h4.y, l4.y);
        Qs2[(k4 * 4 + 2) * 17 + r] = make_float2(h4.z, l4.z);
        Qs2[(k4 * 4 + 3) * 17 + r] = make_float2(h4.w, l4.w);
    }
    __syncthreads();

    // ---- pass 1: scores = 3xTF32, warp w covers keys [w*128, +128) ----
    {
        float acc[16][4] = {};
        const float2* KTl = KTb + (size_t)tig * T_ + w * 128 + gid;
        for (int ksc = 0; ksc < 16; ksc++) {
            const float2 qa = Qs2[(ksc * 4 + tig) * 17 + gid];      // row gid
            const float2 qb = Qs2[(ksc * 4 + tig) * 17 + gid + 8];  // row gid+8
            const float2* Kk = KTl + (size_t)(ksc * 4) * T_;
            #pragma unroll
            for (int half = 0; half < 2; half++) {
                float2 bb[8];
                #pragma unroll
                for (int nt = 0; nt < 8; nt++)
                    bb[nt] = Kk[(half * 8 + nt) * 8];
                #pragma unroll
                for (int nt = 0; nt < 8; nt++) {
                    float* a = acc[half * 8 + nt];
                    mma_k4(a, qa.x, qb.x, bb[nt].x);   // hi*hi
                    mma_k4(a, qa.x, qb.x, bb[nt].y);   // hi*lo
                    mma_k4(a, qa.y, qb.y, bb[nt].x);   // lo*hi
                }
            }
        }
        #pragma unroll
        for (int nt = 0; nt < 16; nt++) {
            const int col = w * 128 + nt * 8 + tig * 2;
            *(float2*)&P[gid * PST + col]       = make_float2(acc[nt][0], acc[nt][1]);
            *(float2*)&P[(gid + 8) * PST + col] = make_float2(acc[nt][2], acc[nt][3]);
        }
    }
    __syncthreads();

    // ---- sweep: one warp per row: max, exp+sum, threshold+rna ----
    {
        float4* Pr = (float4*)(P + w * PST);
        float m = -1e30f;
        #pragma unroll 4
        for (int j = lane; j < 512; j += 32) {
            const float4 v = Pr[j];
            m = fmaxf(m, fmaxf(fmaxf(v.x, v.y), fmaxf(v.z, v.w)));
        }
        #pragma unroll
        for (int o = 16; o; o >>= 1) m = fmaxf(m, __shfl_xor_sync(0xffffffffu, m, o));
        float s = 0.f;
        #pragma unroll 4
        for (int j = lane; j < 512; j += 32) {
            float4 v = Pr[j];
            v.x = __expf(v.x - m); v.y = __expf(v.y - m);
            v.z = __expf(v.z - m); v.w = __expf(v.w - m);
            Pr[j] = v;
            s += (v.x + v.y) + (v.z + v.w);
        }
        #pragma unroll
        for (int o = 16; o; o >>= 1) s += __shfl_xor_sync(0xffffffffu, s, o);
        const float thr = s * (1.0f / 2048.0f);
        #pragma unroll 4
        for (int j = lane; j < 512; j += 32) {
            float4 v = Pr[j];
            v.x = (v.x > thr) ? tf32_rna(v.x) : 0.f;
            v.y = (v.y > thr) ? tf32_rna(v.y) : 0.f;
            v.z = (v.z > thr) ? tf32_rna(v.z) : 0.f;
            v.w = (v.w > thr) ? tf32_rna(v.w) : 0.f;
            Pr[j] = v;
        }
        if (lane == 0) Srow[w] = s;
    }
    __syncthreads();

    // ---- pass 2: out = P_thr @ V, warp w takes k = vt*128 + w*8 + {tig,tig+4} ----
    {
        float acc2[8][4] = {};
        for (int vt = 0; vt < 16; vt++) {
            // stage V tile as pairs: Vs2[p][d] = (V[klow][d], V[klow+4][d]),
            // p = 0..63, klow = (p>>2)*8 + (p&3)
            #pragma unroll
            for (int i = 0; i < 8; i++) {
                const int idx = tid + i * 512;      // 4096 slots
                const int p = idx >> 6, d = idx & 63;
                const int klow = (p >> 2) * 8 + (p & 3);
                const float vlo = Vb[((size_t)vt * 128 + klow) * DK_ + d];
                const float vhi = Vb[((size_t)vt * 128 + klow + 4) * DK_ + d];
                Vs2[p * VST + d] = make_float2(vlo, vhi);
            }
            __syncthreads();
            const int kg = vt * 128 + w * 8 + tig;
            const float a0 = P[gid * PST + kg];
            const float a1 = P[(gid + 8) * PST + kg];
            const float a2 = P[gid * PST + kg + 4];
            const float a3 = P[(gid + 8) * PST + kg + 4];
            const float2* Vp = Vs2 + (w * 4 + tig) * VST + gid;
            #pragma unroll
            for (int nt = 0; nt < 8; nt++) {
                const float2 bv = Vp[nt * 8];
                mma_k8(acc2[nt], a0, a1, a2, a3, bv.x, bv.y);
            }
            __syncthreads();
        }
        // partial sums -> redbuf[w][16*64]
        #pragma unroll
        for (int nt = 0; nt < 8; nt++) {
            const int col = nt * 8 + tig * 2;
            *(float2*)&redbuf[w * 1024 + gid * 64 + col] =
                make_float2(acc2[nt][0], acc2[nt][1]);
            *(float2*)&redbuf[w * 1024 + (gid + 8) * 64 + col] =
                make_float2(acc2[nt][2], acc2[nt][3]);
        }
    }
    __syncthreads();

    // ---- final reduce over 16 warps, divide by S, store ----
    {
        const int o = tid * 2;
        const int r = o >> 6, c = o & 63;
        float s0 = 0.f, s1 = 0.f;
        #pragma unroll
        for (int gg = 0; gg < 16; gg++) {
            const float2 v = *(const float2*)&redbuf[gg * 1024 + o];
            s0 += v.x; s1 += v.y;
        }
        const float inv = 1.0f / Srow[r];
        const int bb = bh >> 3, hh = bh & 7;
        *(float2*)&Og[((size_t)(bb * T_ + row0 + r)) * D_ + hh * 64 + c] =
            make_float2(s0 * inv, s1 * inv);
    }
}

// ---------------------------------------------------------------------------
extern "C" void kernel_launch(void* const* d_in, const int* in_sizes, int n_in,
                              void* d_out, int out_size) {
    const float* q  = (const float*)d_in[0];
    const float* k  = (const float*)d_in[1];
    const float* v  = (const float*)d_in[2];
    const float* Wq = (const float*)d_in[3];
    const float* bq = (const float*)d_in[4];
    const float* Wk = (const float*)d_in[5];
    const float* bk = (const float*)d_in[6];
    const float* Wv = (const float*)d_in[7];
    const float* bv = (const float*)d_in[8];
    const float* Wo = (const float*)d_in[9];
    const float* bo = (const float*)d_in[10];
    float* out = (float*)d_out;

    float *gQ, *gQlo, *gKT, *gV, *gO;
    cudaGetSymbolAddress((void**)&gQ, g_Q);
    cudaGetSymbolAddress((void**)&gQlo, g_Qlo);
    cudaGetSymbolAddress((void**)&gKT, g_KT);
    cudaGetSymbolAddress((void**)&gV, g_V);
    cudaGetSymbolAddress((void**)&gO, g_O);

    cudaFuncSetAttribute(attn_kernel, cudaFuncAttributeMaxDynamicSharedMemorySize,
                         ATTN_SMEM_BYTES);

    proj_kernel<<<dim3(32, 4, 3), 256>>>(q, k, v, Wq, bq, Wk, bk, Wv, bv,
                                         gQ, gQlo, gKT, gV);
    attn_kernel<<<dim3(128, 16), 512, ATTN_SMEM_BYTES>>>(
        gQ, gQlo, (const float2*)gKT, gV, gO);
    outproj_kernel<<<dim3(32, 4), 256>>>(gO, Wo, bo, out);
}

// round 8
// speedup vs baseline: 2.4359x; 1.1173x over previous
#include <cuda_runtime.h>
#include <cstdint>

#define B_  2
#define T_  2048
#define D_  512
#define H_  8
#define DK_ 64

__device__ float g_Q  [B_ * H_ * T_ * DK_];   // [bh][t][k] tf32 hi
__device__ float g_Qlo[B_ * H_ * T_ * DK_];   // [bh][t][k] residual
__device__ float g_KT [B_ * H_ * DK_ * T_];   // [bh][k][t] fp32 (split on the fly)
__device__ float g_V  [B_ * H_ * T_ * DK_];   // [bh][t][k] rna tf32
__device__ float g_O  [B_ * T_ * D_];

__device__ __forceinline__ float tf32_rna(float x) {
    uint32_t r;
    asm("cvt.rna.tf32.f32 %0, %1;" : "=r"(r) : "f"(x));
    return __uint_as_float(r);
}
__device__ __forceinline__ void mma_k4(float* d, float a0, float a1, float b0) {
    asm volatile(
        "mma.sync.aligned.m16n8k4.row.col.f32.tf32.tf32.f32 "
        "{%0,%1,%2,%3}, {%4,%5}, {%6}, {%0,%1,%2,%3};\n"
        : "+f"(d[0]), "+f"(d[1]), "+f"(d[2]), "+f"(d[3])
        : "r"(__float_as_uint(a0)), "r"(__float_as_uint(a1)),
          "r"(__float_as_uint(b0)));
}
__device__ __forceinline__ void mma_k8(float* d, float a0, float a1, float a2,
                                       float a3, float b0, float b1) {
    asm volatile(
        "mma.sync.aligned.m16n8k8.row.col.f32.tf32.tf32.f32 "
        "{%0,%1,%2,%3}, {%4,%5,%6,%7}, {%8,%9}, {%0,%1,%2,%3};\n"
        : "+f"(d[0]), "+f"(d[1]), "+f"(d[2]), "+f"(d[3])
        : "r"(__float_as_uint(a0)), "r"(__float_as_uint(a1)),
          "r"(__float_as_uint(a2)), "r"(__float_as_uint(a3)),
          "r"(__float_as_uint(b0)), "r"(__float_as_uint(b1)));
}

// ---------------------------------------------------------------------------
// GEMM Y = X@W^T + bias. 128x128 tile, 256 thr, 8x8 microtile, prefetch.
// Shared buffers passed in (one static allocation per kernel).
// MODE 0: Q -> hi(Y) + lo(Ylo), head layout
// MODE 1: K -> transposed fp32 [bh][k][t]
// MODE 2: V -> rna-rounded, head layout
// MODE 3: flat [m][512]
// ---------------------------------------------------------------------------
template <int MODE>
__device__ __forceinline__ void gemm128(const float* __restrict__ X,
                                        const float* __restrict__ W,
                                        const float* __restrict__ bias,
                                        float* __restrict__ Y,
                                        float* __restrict__ Ylo,
                                        float* __restrict__ Xs,
                                        float* __restrict__ Ws) {
    const int tid = threadIdx.x;
    const int rg = tid >> 4, cg = tid & 15;
    const int m0 = blockIdx.x * 128, n0 = blockIdx.y * 128;
    const int mm0 = tid >> 2,         kk40 = tid & 3;
    const int mm1 = (tid + 256) >> 2, kk41 = (tid + 256) & 3;

    float acc[8][8] = {};
    float4 xr0, xr1, wr0, wr1;
    xr0 = *(const float4*)&X[(size_t)(m0 + mm0) * 512 + kk40 * 4];
    xr1 = *(const float4*)&X[(size_t)(m0 + mm1) * 512 + kk41 * 4];
    wr0 = *(const float4*)&W[(size_t)(n0 + mm0) * 512 + kk40 * 4];
    wr1 = *(const float4*)&W[(size_t)(n0 + mm1) * 512 + kk41 * 4];

    for (int kt = 0; kt < 512; kt += 16) {
        __syncthreads();
        Xs[(kk40 * 4 + 0) * 132 + mm0] = xr0.x;
        Xs[(kk40 * 4 + 1) * 132 + mm0] = xr0.y;
        Xs[(kk40 * 4 + 2) * 132 + mm0] = xr0.z;
        Xs[(kk40 * 4 + 3) * 132 + mm0] = xr0.w;
        Xs[(kk41 * 4 + 0) * 132 + mm1] = xr1.x;
        Xs[(kk41 * 4 + 1) * 132 + mm1] = xr1.y;
        Xs[(kk41 * 4 + 2) * 132 + mm1] = xr1.z;
        Xs[(kk41 * 4 + 3) * 132 + mm1] = xr1.w;
        Ws[(kk40 * 4 + 0) * 132 + mm0] = wr0.x;
        Ws[(kk40 * 4 + 1) * 132 + mm0] = wr0.y;
        Ws[(kk40 * 4 + 2) * 132 + mm0] = wr0.z;
        Ws[(kk40 * 4 + 3) * 132 + mm0] = wr0.w;
        Ws[(kk41 * 4 + 0) * 132 + mm1] = wr1.x;
        Ws[(kk41 * 4 + 1) * 132 + mm1] = wr1.y;
        Ws[(kk41 * 4 + 2) * 132 + mm1] = wr1.z;
        Ws[(kk41 * 4 + 3) * 132 + mm1] = wr1.w;
        __syncthreads();
        if (kt + 16 < 512) {
            const int kn = kt + 16;
            xr0 = *(const float4*)&X[(size_t)(m0 + mm0) * 512 + kn + kk40 * 4];
            xr1 = *(const float4*)&X[(size_t)(m0 + mm1) * 512 + kn + kk41 * 4];
            wr0 = *(const float4*)&W[(size_t)(n0 + mm0) * 512 + kn + kk40 * 4];
            wr1 = *(const float4*)&W[(size_t)(n0 + mm1) * 512 + kn + kk41 * 4];
        }
        #pragma unroll
        for (int kk = 0; kk < 16; kk++) {
            const float4 a0 = *(const float4*)&Xs[kk * 132 + rg * 4];
            const float4 a1 = *(const float4*)&Xs[kk * 132 + 64 + rg * 4];
            const float4 b0 = *(const float4*)&Ws[kk * 132 + cg * 4];
            const float4 b1 = *(const float4*)&Ws[kk * 132 + 64 + cg * 4];
            const float av[8] = {a0.x, a0.y, a0.z, a0.w, a1.x, a1.y, a1.z, a1.w};
            const float bv[8] = {b0.x, b0.y, b0.z, b0.w, b1.x, b1.y, b1.z, b1.w};
            #pragma unroll
            for (int i = 0; i < 8; i++)
                #pragma unroll
                for (int j = 0; j < 8; j++)
                    acc[i][j] = fmaf(av[i], bv[j], acc[i][j]);
        }
    }

    const float4 bb0 = *(const float4*)&bias[n0 + cg * 4];
    const float4 bb1 = *(const float4*)&bias[n0 + 64 + cg * 4];
    const float bias8[8] = {bb0.x, bb0.y, bb0.z, bb0.w, bb1.x, bb1.y, bb1.z, bb1.w};
    #pragma unroll
    for (int ih = 0; ih < 2; ih++) {
        #pragma unroll
        for (int i = 0; i < 4; i++) {
            const int m = m0 + ih * 64 + rg * 4 + i;
            const int b = m >> 11;
            const int t = m & (T_ - 1);
            float o[8];
            #pragma unroll
            for (int j = 0; j < 8; j++) o[j] = acc[ih * 4 + i][j] + bias8[j];

            if (MODE == 3) {
                *(float4*)&Y[(size_t)m * 512 + n0 + cg * 4] =
                    make_float4(o[0], o[1], o[2], o[3]);
                *(float4*)&Y[(size_t)m * 512 + n0 + 64 + cg * 4] =
                    make_float4(o[4], o[5], o[6], o[7]);
            } else if (MODE == 1) {
                #pragma unroll
                for (int j = 0; j < 8; j++) {
                    const int col = n0 + (j < 4 ? 0 : 64) + cg * 4 + (j & 3);
                    Y[((size_t)((b * H_ + (col >> 6)) * DK_ + (col & 63))) * T_ + t] =
                        o[j];
                }
            } else {
                #pragma unroll
                for (int half = 0; half < 2; half++) {
                    const int col = n0 + half * 64 + cg * 4;
                    const size_t base =
                        (((size_t)(b * H_ + (col >> 6))) * T_ + t) * DK_ + (col & 63);
                    float4 h4, l4;
                    float* hp = (float*)&h4;
                    float* lp = (float*)&l4;
                    #pragma unroll
                    for (int j = 0; j < 4; j++) {
                        const float v = o[half * 4 + j];
                        hp[j] = tf32_rna(v);
                        lp[j] = v - hp[j];
                    }
                    *(float4*)&Y[base] = h4;
                    if (MODE == 0) *(float4*)&Ylo[base] = l4;
                }
            }
        }
    }
}

__global__ __launch_bounds__(256)
void proj_kernel(const float* __restrict__ q, const float* __restrict__ k,
                 const float* __restrict__ v,
                 const float* __restrict__ Wq, const float* __restrict__ bq,
                 const float* __restrict__ Wk, const float* __restrict__ bk,
                 const float* __restrict__ Wv, const float* __restrict__ bv,
                 float* __restrict__ gQ, float* __restrict__ gQlo,
                 float* __restrict__ gKT, float* __restrict__ gV) {
    __shared__ float Xs[16 * 132];
    __shared__ float Ws[16 * 132];
    if (blockIdx.z == 0)      gemm128<0>(q, Wq, bq, gQ, gQlo, Xs, Ws);
    else if (blockIdx.z == 1) gemm128<1>(k, Wk, bk, gKT, nullptr, Xs, Ws);
    else                      gemm128<2>(v, Wv, bv, gV, nullptr, Xs, Ws);
}

__global__ __launch_bounds__(256)
void outproj_kernel(const float* __restrict__ X, const float* __restrict__ W,
                    const float* __restrict__ bias, float* __restrict__ Y) {
    __shared__ float Xs[16 * 132];
    __shared__ float Ws[16 * 132];
    gemm128<3>(X, W, bias, Y, nullptr, Xs, Ws);
}

// ---------------------------------------------------------------------------
// Attention (tf32 tensor cores): 16 rows/block, 512 threads, 16 warps.
// Smem floats: P[16][2052] @0 | VS region (Vs2 f2[64][72] / redbuf[16][1024])
// @32832 | Qs2 f2[64][17] @49216 | Srow[16] @51392  => 205,632 B
// ---------------------------------------------------------------------------
#define PST      2052
#define VS_OFF   32832
#define QS_OFF   49216
#define SROW_OFF 51392
#define ATTN_SMEM_BYTES ((SROW_OFF + 16) * 4)
#define VST 72

__global__ __launch_bounds__(512)
void attn_kernel(const float* __restrict__ Qh, const float* __restrict__ Qlo,
                 const float* __restrict__ KT, const float* __restrict__ Vh,
                 float* __restrict__ Og) {
    extern __shared__ float sm[];
    float*  P      = sm;
    float2* Vs2    = (float2*)(sm + VS_OFF);
    float*  redbuf = sm + VS_OFF;
    float2* Qs2    = (float2*)(sm + QS_OFF);   // [k][r] stride 17
    float*  Srow   = sm + SROW_OFF;

    const int tid  = threadIdx.x;
    const int w    = tid >> 5;
    const int lane = tid & 31;
    const int gid  = lane >> 2;     // 0..7
    const int tig  = lane & 3;      // 0..3
    const int bh   = blockIdx.y;
    const int row0 = blockIdx.x * 16;

    const float* Qb  = Qh  + ((size_t)bh * T_ + row0) * DK_;
    const float* Qlb = Qlo + ((size_t)bh * T_ + row0) * DK_;
    const float* KTb = KT  + (size_t)bh * DK_ * T_;
    const float* Vb  = Vh  + (size_t)bh * T_ * DK_;

    if (tid < 256) {
        const int r = tid & 15, k4 = tid >> 4;
        const float4 h4 = *(const float4*)&Qb [(size_t)r * DK_ + k4 * 4];
        const float4 l4 = *(const float4*)&Qlb[(size_t)r * DK_ + k4 * 4];
        Qs2[(k4 * 4 + 0) * 17 + r] = make_float2(h4.x, l4.x);
        Qs2[(k4 * 4 + 1) * 17 + r] = make_float2(h4.y, l4.y);
        Qs2[(k4 * 4 + 2) * 17 + r] = make_float2(h4.z, l4.z);
        Qs2[(k4 * 4 + 3) * 17 + r] = make_float2(h4.w, l4.w);
    }
    __syncthreads();

    // ---- pass 1: 3xTF32 scores; K loaded fp32, hi/lo split on the fly ----
    {
        float acc[16][4] = {};
        const float* KTl = KTb + (size_t)tig * T_ + w * 128 + gid;
        for (int ksc = 0; ksc < 16; ksc++) {
            const float2 qa = Qs2[(ksc * 4 + tig) * 17 + gid];      // row gid
            const float2 qb = Qs2[(ksc * 4 + tig) * 17 + gid + 8];  // row gid+8
            const float* Kk = KTl + (size_t)(ksc * 4) * T_;
            #pragma unroll
            for (int half = 0; half < 2; half++) {
                float bk[8];
                #pragma unroll
                for (int nt = 0; nt < 8; nt++)
                    bk[nt] = Kk[(half * 8 + nt) * 8];
                #pragma unroll
                for (int nt = 0; nt < 8; nt++) {
                    float* a = acc[half * 8 + nt];
                    const float hi = tf32_rna(bk[nt]);
                    const float lo = bk[nt] - hi;
                    mma_k4(a, qa.x, qb.x, hi);   // qhi * khi
                    mma_k4(a, qa.x, qb.x, lo);   // qhi * klo
                    mma_k4(a, qa.y, qb.y, hi);   // qlo * khi
                }
            }
        }
        #pragma unroll
        for (int nt = 0; nt < 16; nt++) {
            const int col = w * 128 + nt * 8 + tig * 2;
            *(float2*)&P[gid * PST + col]       = make_float2(acc[nt][0], acc[nt][1]);
            *(float2*)&P[(gid + 8) * PST + col] = make_float2(acc[nt][2], acc[nt][3]);
        }
    }
    __syncthreads();

    // ---- sweep: one warp per row: max, exp+sum, threshold+rna ----
    {
        float4* Pr = (float4*)(P + w * PST);
        float m = -1e30f;
        #pragma unroll 4
        for (int j = lane; j < 512; j += 32) {
            const float4 v = Pr[j];
            m = fmaxf(m, fmaxf(fmaxf(v.x, v.y), fmaxf(v.z, v.w)));
        }
        #pragma unroll
        for (int o = 16; o; o >>= 1) m = fmaxf(m, __shfl_xor_sync(0xffffffffu, m, o));
        float s = 0.f;
        #pragma unroll 4
        for (int j = lane; j < 512; j += 32) {
            float4 v = Pr[j];
            v.x = __expf(v.x - m); v.y = __expf(v.y - m);
            v.z = __expf(v.z - m); v.w = __expf(v.w - m);
            Pr[j] = v;
            s += (v.x + v.y) + (v.z + v.w);
        }
        #pragma unroll
        for (int o = 16; o; o >>= 1) s += __shfl_xor_sync(0xffffffffu, s, o);
        const float thr = s * (1.0f / 2048.0f);
        #pragma unroll 4
        for (int j = lane; j < 512; j += 32) {
            float4 v = Pr[j];
            v.x = (v.x > thr) ? tf32_rna(v.x) : 0.f;
            v.y = (v.y > thr) ? tf32_rna(v.y) : 0.f;
            v.z = (v.z > thr) ? tf32_rna(v.z) : 0.f;
            v.w = (v.w > thr) ? tf32_rna(v.w) : 0.f;
            Pr[j] = v;
        }
        if (lane == 0) Srow[w] = s;
    }
    __syncthreads();

    // ---- pass 2: out = P_thr @ V (register-double-buffered V tiles) ----
    // stage tile as pairs: Vs2[p][d] = (V[klow][d], V[klow+4][d]),
    //   p = 0..63, klow = (p>>2)*8 + (p&3)
    // warp w consumes k = vt*128 + w*8 + {tig, tig+4}
    {
        float acc2[8][4] = {};
        float2 pre[8];

        // prefetch tile 0: this thread owns slots idx = tid + i*512
        #pragma unroll
        for (int i = 0; i < 8; i++) {
            const int idx = tid + i * 512;
            const int pp = idx >> 6, d = idx & 63;
            const int klow = (pp >> 2) * 8 + (pp & 3);
            pre[i] = make_float2(Vb[(size_t)klow * DK_ + d],
                                 Vb[(size_t)(klow + 4) * DK_ + d]);
        }

        for (int vt = 0; vt < 16; vt++) {
            #pragma unroll
            for (int i = 0; i < 8; i++) {
                const int idx = tid + i * 512;
                const int pp = idx >> 6, d = idx & 63;
                Vs2[pp * VST + d] = pre[i];
            }
            __syncthreads();
            if (vt < 15) {
                #pragma unroll
                for (int i = 0; i < 8; i++) {
                    const int idx = tid + i * 512;
                    const int pp = idx >> 6, d = idx & 63;
                    const int klow = (pp >> 2) * 8 + (pp & 3);
                    pre[i] = make_float2(
                        Vb[((size_t)(vt + 1) * 128 + klow) * DK_ + d],
                        Vb[((size_t)(vt + 1) * 128 + klow + 4) * DK_ + d]);
                }
            }
            const int kg = vt * 128 + w * 8 + tig;
            const float a0 = P[gid * PST + kg];
            const float a1 = P[(gid + 8) * PST + kg];
            const float a2 = P[gid * PST + kg + 4];
            const float a3 = P[(gid + 8) * PST + kg + 4];
            const float2* Vp = Vs2 + (w * 4 + tig) * VST + gid;
            #pragma unroll
            for (int nt = 0; nt < 8; nt++) {
                const float2 bv = Vp[nt * 8];
                mma_k8(acc2[nt], a0, a1, a2, a3, bv.x, bv.y);
            }
            __syncthreads();
        }
        // partial sums -> redbuf[w][16*64]
        #pragma unroll
        for (int nt = 0; nt < 8; nt++) {
            const int col = nt * 8 + tig * 2;
            *(float2*)&redbuf[w * 1024 + gid * 64 + col] =
                make_float2(acc2[nt][0], acc2[nt][1]);
            *(float2*)&redbuf[w * 1024 + (gid + 8) * 64 + col] =
                make_float2(acc2[nt][2], acc2[nt][3]);
        }
    }
    __syncthreads();

    // ---- final reduce over 16 warps, divide by S, store ----
    {
        const int o = tid * 2;
        const int r = o >> 6, c = o & 63;
        float s0 = 0.f, s1 = 0.f;
        #pragma unroll
        for (int gg = 0; gg < 16; gg++) {
            const float2 v = *(const float2*)&redbuf[gg * 1024 + o];
            s0 += v.x; s1 += v.y;
        }
        const float inv = 1.0f / Srow[r];
        const int bb = bh >> 3, hh = bh & 7;
        *(float2*)&Og[((size_t)(bb * T_ + row0 + r)) * D_ + hh * 64 + c] =
            make_float2(s0 * inv, s1 * inv);
    }
}

// ---------------------------------------------------------------------------
extern "C" void kernel_launch(void* const* d_in, const int* in_sizes, int n_in,
                              void* d_out, int out_size) {
    const float* q  = (const float*)d_in[0];
    const float* k  = (const float*)d_in[1];
    const float* v  = (const float*)d_in[2];
    const float* Wq = (const float*)d_in[3];
    const float* bq = (const float*)d_in[4];
    const float* Wk = (const float*)d_in[5];
    const float* bk = (const float*)d_in[6];
    const float* Wv = (const float*)d_in[7];
    const float* bv = (const float*)d_in[8];
    const float* Wo = (const float*)d_in[9];
    const float* bo = (const float*)d_in[10];
    float* out = (float*)d_out;

    float *gQ, *gQlo, *gKT, *gV, *gO;
    cudaGetSymbolAddress((void**)&gQ, g_Q);
    cudaGetSymbolAddress((void**)&gQlo, g_Qlo);
    cudaGetSymbolAddress((void**)&gKT, g_KT);
    cudaGetSymbolAddress((void**)&gV, g_V);
    cudaGetSymbolAddress((void**)&gO, g_O);

    cudaFuncSetAttribute(attn_kernel, cudaFuncAttributeMaxDynamicSharedMemorySize,
                         ATTN_SMEM_BYTES);

    proj_kernel<<<dim3(32, 4, 3), 256>>>(q, k, v, Wq, bq, Wk, bk, Wv, bv,
                                         gQ, gQlo, gKT, gV);
    attn_kernel<<<dim3(128, 16), 512, ATTN_SMEM_BYTES>>>(gQ, gQlo, gKT, gV, gO);
    outproj_kernel<<<dim3(32, 4), 256>>>(gO, Wo, bo, out);
}

// round 10
// speedup vs baseline: 2.6217x; 1.0762x over previous
#include <cuda_runtime.h>
#include <cstdint>

#define B_  2
#define T_  2048
#define D_  512
#define H_  8
#define DK_ 64

__device__ float g_Q  [B_ * H_ * T_ * DK_];   // [bh][t][k] tf32 hi
__device__ float g_Qlo[B_ * H_ * T_ * DK_];   // [bh][t][k] residual
__device__ float g_KT [B_ * H_ * DK_ * T_];   // [bh][k][t] fp32 (split on the fly)
__device__ float g_V  [B_ * H_ * T_ * DK_];   // [bh][t][k] tf32-rounded
__device__ float g_O  [B_ * T_ * D_];

__device__ __forceinline__ float tf32_rna(float x) {
    uint32_t r;
    asm("cvt.rna.tf32.f32 %0, %1;" : "=r"(r) : "f"(x));
    return __uint_as_float(r);
}
__device__ __forceinline__ void mma_k4(float* d, float a0, float a1, float b0) {
    asm volatile(
        "mma.sync.aligned.m16n8k4.row.col.f32.tf32.tf32.f32 "
        "{%0,%1,%2,%3}, {%4,%5}, {%6}, {%0,%1,%2,%3};\n"
        : "+f"(d[0]), "+f"(d[1]), "+f"(d[2]), "+f"(d[3])
        : "r"(__float_as_uint(a0)), "r"(__float_as_uint(a1)),
          "r"(__float_as_uint(b0)));
}
__device__ __forceinline__ void mma_k8(float* d, float a0, float a1, float a2,
                                       float a3, float b0, float b1) {
    asm volatile(
        "mma.sync.aligned.m16n8k8.row.col.f32.tf32.tf32.f32 "
        "{%0,%1,%2,%3}, {%4,%5,%6,%7}, {%8,%9}, {%0,%1,%2,%3};\n"
        : "+f"(d[0]), "+f"(d[1]), "+f"(d[2]), "+f"(d[3])
        : "r"(__float_as_uint(a0)), "r"(__float_as_uint(a1)),
          "r"(__float_as_uint(a2)), "r"(__float_as_uint(a3)),
          "r"(__float_as_uint(b0)), "r"(__float_as_uint(b1)));
}

// ---------------------------------------------------------------------------
// GEMM Y = X@W^T + bias. 128x128 tile, 256 thr, 8x8 microtile, prefetch.
// Shared buffers passed in (one static allocation per kernel).
// MODE 0: Q -> hi(Y) + lo(Ylo), head layout
// MODE 1: K -> transposed fp32 [bh][k][t]
// MODE 2: V -> tf32(rna)-rounded, head layout
// MODE 3: flat [m][512]
// ---------------------------------------------------------------------------
template <int MODE>
__device__ __forceinline__ void gemm128(const float* __restrict__ X,
                                        const float* __restrict__ W,
                                        const float* __restrict__ bias,
                                        float* __restrict__ Y,
                                        float* __restrict__ Ylo,
                                        float* __restrict__ Xs,
                                        float* __restrict__ Ws) {
    const int tid = threadIdx.x;
    const int rg = tid >> 4, cg = tid & 15;
    const int m0 = blockIdx.x * 128, n0 = blockIdx.y * 128;
    const int mm0 = tid >> 2,         kk40 = tid & 3;
    const int mm1 = (tid + 256) >> 2, kk41 = (tid + 256) & 3;

    float acc[8][8] = {};
    float4 xr0, xr1, wr0, wr1;
    xr0 = *(const float4*)&X[(size_t)(m0 + mm0) * 512 + kk40 * 4];
    xr1 = *(const float4*)&X[(size_t)(m0 + mm1) * 512 + kk41 * 4];
    wr0 = *(const float4*)&W[(size_t)(n0 + mm0) * 512 + kk40 * 4];
    wr1 = *(const float4*)&W[(size_t)(n0 + mm1) * 512 + kk41 * 4];

    for (int kt = 0; kt < 512; kt += 16) {
        __syncthreads();
        Xs[(kk40 * 4 + 0) * 132 + mm0] = xr0.x;
        Xs[(kk40 * 4 + 1) * 132 + mm0] = xr0.y;
        Xs[(kk40 * 4 + 2) * 132 + mm0] = xr0.z;
        Xs[(kk40 * 4 + 3) * 132 + mm0] = xr0.w;
        Xs[(kk41 * 4 + 0) * 132 + mm1] = xr1.x;
        Xs[(kk41 * 4 + 1) * 132 + mm1] = xr1.y;
        Xs[(kk41 * 4 + 2) * 132 + mm1] = xr1.z;
        Xs[(kk41 * 4 + 3) * 132 + mm1] = xr1.w;
        Ws[(kk40 * 4 + 0) * 132 + mm0] = wr0.x;
        Ws[(kk40 * 4 + 1) * 132 + mm0] = wr0.y;
        Ws[(kk40 * 4 + 2) * 132 + mm0] = wr0.z;
        Ws[(kk40 * 4 + 3) * 132 + mm0] = wr0.w;
        Ws[(kk41 * 4 + 0) * 132 + mm1] = wr1.x;
        Ws[(kk41 * 4 + 1) * 132 + mm1] = wr1.y;
        Ws[(kk41 * 4 + 2) * 132 + mm1] = wr1.z;
        Ws[(kk41 * 4 + 3) * 132 + mm1] = wr1.w;
        __syncthreads();
        if (kt + 16 < 512) {
            const int kn = kt + 16;
            xr0 = *(const float4*)&X[(size_t)(m0 + mm0) * 512 + kn + kk40 * 4];
            xr1 = *(const float4*)&X[(size_t)(m0 + mm1) * 512 + kn + kk41 * 4];
            wr0 = *(const float4*)&W[(size_t)(n0 + mm0) * 512 + kn + kk40 * 4];
            wr1 = *(const float4*)&W[(size_t)(n0 + mm1) * 512 + kn + kk41 * 4];
        }
        #pragma unroll
        for (int kk = 0; kk < 16; kk++) {
            const float4 a0 = *(const float4*)&Xs[kk * 132 + rg * 4];
            const float4 a1 = *(const float4*)&Xs[kk * 132 + 64 + rg * 4];
            const float4 b0 = *(const float4*)&Ws[kk * 132 + cg * 4];
            const float4 b1 = *(const float4*)&Ws[kk * 132 + 64 + cg * 4];
            const float av[8] = {a0.x, a0.y, a0.z, a0.w, a1.x, a1.y, a1.z, a1.w};
            const float bv[8] = {b0.x, b0.y, b0.z, b0.w, b1.x, b1.y, b1.z, b1.w};
            #pragma unroll
            for (int i = 0; i < 8; i++)
                #pragma unroll
                for (int j = 0; j < 8; j++)
                    acc[i][j] = fmaf(av[i], bv[j], acc[i][j]);
        }
    }

    const float4 bb0 = *(const float4*)&bias[n0 + cg * 4];
    const float4 bb1 = *(const float4*)&bias[n0 + 64 + cg * 4];
    const float bias8[8] = {bb0.x, bb0.y, bb0.z, bb0.w, bb1.x, bb1.y, bb1.z, bb1.w};
    #pragma unroll
    for (int ih = 0; ih < 2; ih++) {
        #pragma unroll
        for (int i = 0; i < 4; i++) {
            const int m = m0 + ih * 64 + rg * 4 + i;
            const int b = m >> 11;
            const int t = m & (T_ - 1);
            float o[8];
            #pragma unroll
            for (int j = 0; j < 8; j++) o[j] = acc[ih * 4 + i][j] + bias8[j];

            if (MODE == 3) {
                *(float4*)&Y[(size_t)m * 512 + n0 + cg * 4] =
                    make_float4(o[0], o[1], o[2], o[3]);
                *(float4*)&Y[(size_t)m * 512 + n0 + 64 + cg * 4] =
                    make_float4(o[4], o[5], o[6], o[7]);
            } else if (MODE == 1) {
                #pragma unroll
                for (int j = 0; j < 8; j++) {
                    const int col = n0 + (j < 4 ? 0 : 64) + cg * 4 + (j & 3);
                    Y[((size_t)((b * H_ + (col >> 6)) * DK_ + (col & 63))) * T_ + t] =
                        o[j];
                }
            } else if (MODE == 2) {
                #pragma unroll
                for (int half = 0; half < 2; half++) {
                    const int col = n0 + half * 64 + cg * 4;
                    const size_t base =
                        (((size_t)(b * H_ + (col >> 6))) * T_ + t) * DK_ + (col & 63);
                    float4 r4;
                    float* rp = (float*)&r4;
                    #pragma unroll
                    for (int j = 0; j < 4; j++)
                        rp[j] = tf32_rna(o[half * 4 + j]);
                    *(float4*)&Y[base] = r4;
                }
            } else {   // MODE 0: Q hi/lo
                #pragma unroll
                for (int half = 0; half < 2; half++) {
                    const int col = n0 + half * 64 + cg * 4;
                    const size_t base =
                        (((size_t)(b * H_ + (col >> 6))) * T_ + t) * DK_ + (col & 63);
                    float4 h4, l4;
                    float* hp = (float*)&h4;
                    float* lp = (float*)&l4;
                    #pragma unroll
                    for (int j = 0; j < 4; j++) {
                        const float v = o[half * 4 + j];
                        hp[j] = tf32_rna(v);
                        lp[j] = v - hp[j];
                    }
                    *(float4*)&Y[base] = h4;
                    *(float4*)&Ylo[base] = l4;
                }
            }
        }
    }
}

__global__ __launch_bounds__(256)
void proj_kernel(const float* __restrict__ q, const float* __restrict__ k,
                 const float* __restrict__ v,
                 const float* __restrict__ Wq, const float* __restrict__ bq,
                 const float* __restrict__ Wk, const float* __restrict__ bk,
                 const float* __restrict__ Wv, const float* __restrict__ bv,
                 float* __restrict__ gQ, float* __restrict__ gQlo,
                 float* __restrict__ gKT, float* __restrict__ gV) {
    __shared__ float Xs[16 * 132];
    __shared__ float Ws[16 * 132];
    if (blockIdx.z == 0)      gemm128<0>(q, Wq, bq, gQ, gQlo, Xs, Ws);
    else if (blockIdx.z == 1) gemm128<1>(k, Wk, bk, gKT, nullptr, Xs, Ws);
    else                      gemm128<2>(v, Wv, bv, gV, nullptr, Xs, Ws);
}

__global__ __launch_bounds__(256)
void outproj_kernel(const float* __restrict__ X, const float* __restrict__ W,
                    const float* __restrict__ bias, float* __restrict__ Y) {
    __shared__ float Xs[16 * 132];
    __shared__ float Ws[16 * 132];
    gemm128<3>(X, W, bias, Y, nullptr, Xs, Ws);
}

// ---------------------------------------------------------------------------
// Attention (tf32 tensor cores): 16 rows/block, 512 threads, 16 warps.
// 3xTF32 scores (R8-verified numerics) + barrier-free pass 2 (direct-global V).
// Smem floats: P[16][2052] @0 | redbuf[16][1024] @32832 | Qs2 f2[64][17]
// @49216 | Srow[16] @51392  => 205,632 B
// ---------------------------------------------------------------------------
#define PST      2052
#define RED_OFF  32832
#define QS_OFF   49216
#define SROW_OFF 51392
#define ATTN_SMEM_BYTES ((SROW_OFF + 16) * 4)

__global__ __launch_bounds__(512)
void attn_kernel(const float* __restrict__ Qh, const float* __restrict__ Qlo,
                 const float* __restrict__ KT, const float* __restrict__ Vh,
                 float* __restrict__ Og) {
    extern __shared__ float sm[];
    float*  P      = sm;
    float*  redbuf = sm + RED_OFF;
    float2* Qs2    = (float2*)(sm + QS_OFF);   // [k][r] stride 17
    float*  Srow   = sm + SROW_OFF;

    const int tid  = threadIdx.x;
    const int w    = tid >> 5;
    const int lane = tid & 31;
    const int gid  = lane >> 2;     // 0..7
    const int tig  = lane & 3;      // 0..3
    const int bh   = blockIdx.y;
    const int row0 = blockIdx.x * 16;

    const float* Qb  = Qh  + ((size_t)bh * T_ + row0) * DK_;
    const float* Qlb = Qlo + ((size_t)bh * T_ + row0) * DK_;
    const float* KTb = KT  + (size_t)bh * DK_ * T_;
    const float* Vb  = Vh  + (size_t)bh * T_ * DK_;

    if (tid < 256) {
        const int r = tid & 15, k4 = tid >> 4;
        const float4 h4 = *(const float4*)&Qb [(size_t)r * DK_ + k4 * 4];
        const float4 l4 = *(const float4*)&Qlb[(size_t)r * DK_ + k4 * 4];
        Qs2[(k4 * 4 + 0) * 17 + r] = make_float2(h4.x, l4.x);
        Qs2[(k4 * 4 + 1) * 17 + r] = make_float2(h4.y, l4.y);
        Qs2[(k4 * 4 + 2) * 17 + r] = make_float2(h4.z, l4.z);
        Qs2[(k4 * 4 + 3) * 17 + r] = make_float2(h4.w, l4.w);
    }
    __syncthreads();

    // ---- pass 1: 3xTF32 scores; K loaded fp32, hi/lo split on the fly ----
    {
        float acc[16][4] = {};
        const float* KTl = KTb + (size_t)tig * T_ + w * 128 + gid;
        for (int ksc = 0; ksc < 16; ksc++) {
            const float2 qa = Qs2[(ksc * 4 + tig) * 17 + gid];      // row gid
            const float2 qb = Qs2[(ksc * 4 + tig) * 17 + gid + 8];  // row gid+8
            const float* Kk = KTl + (size_t)(ksc * 4) * T_;
            #pragma unroll
            for (int half = 0; half < 2; half++) {
                float bk[8];
                #pragma unroll
                for (int nt = 0; nt < 8; nt++)
                    bk[nt] = Kk[(half * 8 + nt) * 8];
                #pragma unroll
                for (int nt = 0; nt < 8; nt++) {
                    float* a = acc[half * 8 + nt];
                    const float hi = tf32_rna(bk[nt]);
                    const float lo = bk[nt] - hi;
                    mma_k4(a, qa.x, qb.x, hi);   // qhi * khi
                    mma_k4(a, qa.x, qb.x, lo);   // qhi * klo
                    mma_k4(a, qa.y, qb.y, hi);   // qlo * khi
                }
            }
        }
        #pragma unroll
        for (int nt = 0; nt < 16; nt++) {
            const int col = w * 128 + nt * 8 + tig * 2;
            *(float2*)&P[gid * PST + col]       = make_float2(acc[nt][0], acc[nt][1]);
            *(float2*)&P[(gid + 8) * PST + col] = make_float2(acc[nt][2], acc[nt][3]);
        }
    }
    __syncthreads();

    // ---- sweep: one warp per row: max, exp+sum, threshold+rna ----
    {
        float4* Pr = (float4*)(P + w * PST);
        float m = -1e30f;
        #pragma unroll 4
        for (int j = lane; j < 512; j += 32) {
            const float4 v = Pr[j];
            m = fmaxf(m, fmaxf(fmaxf(v.x, v.y), fmaxf(v.z, v.w)));
        }
        #pragma unroll
        for (int o = 16; o; o >>= 1) m = fmaxf(m, __shfl_xor_sync(0xffffffffu, m, o));
        float s = 0.f;
        #pragma unroll 4
        for (int j = lane; j < 512; j += 32) {
            float4 v = Pr[j];
            v.x = __expf(v.x - m); v.y = __expf(v.y - m);
            v.z = __expf(v.z - m); v.w = __expf(v.w - m);
            Pr[j] = v;
            s += (v.x + v.y) + (v.z + v.w);
        }
        #pragma unroll
        for (int o = 16; o; o >>= 1) s += __shfl_xor_sync(0xffffffffu, s, o);
        const float thr = s * (1.0f / 2048.0f);
        #pragma unroll 4
        for (int j = lane; j < 512; j += 32) {
            float4 v = Pr[j];
            v.x = (v.x > thr) ? tf32_rna(v.x) : 0.f;
            v.y = (v.y > thr) ? tf32_rna(v.y) : 0.f;
            v.z = (v.z > thr) ? tf32_rna(v.z) : 0.f;
            v.w = (v.w > thr) ? tf32_rna(v.w) : 0.f;
            Pr[j] = v;
        }
        if (lane == 0) Srow[w] = s;
    }
    __syncthreads();

    // ---- pass 2: out = P_thr @ V; V fragments direct from global ----
    // warp w handles k = vt*128 + w*8 + {tig, tig+4}; no barriers in loop.
    {
        float acc2[8][4] = {};
        #pragma unroll 2
        for (int vt = 0; vt < 16; vt++) {
            const int kg = vt * 128 + w * 8 + tig;
            const float a0 = P[gid * PST + kg];
            const float a1 = P[(gid + 8) * PST + kg];
            const float a2 = P[gid * PST + kg + 4];
            const float a3 = P[(gid + 8) * PST + kg + 4];
            const float* Vr0 = Vb + (size_t)kg * DK_ + gid;
            const float* Vr1 = Vb + (size_t)(kg + 4) * DK_ + gid;
            float b0[8], b1[8];
            #pragma unroll
            for (int nt = 0; nt < 8; nt++) {
                b0[nt] = Vr0[nt * 8];
                b1[nt] = Vr1[nt * 8];
            }
            #pragma unroll
            for (int nt = 0; nt < 8; nt++)
                mma_k8(acc2[nt], a0, a1, a2, a3, b0[nt], b1[nt]);
        }
        // partial sums -> redbuf[w][16*64]
        #pragma unroll
        for (int nt = 0; nt < 8; nt++) {
            const int col = nt * 8 + tig * 2;
            *(float2*)&redbuf[w * 1024 + gid * 64 + col] =
                make_float2(acc2[nt][0], acc2[nt][1]);
            *(float2*)&redbuf[w * 1024 + (gid + 8) * 64 + col] =
                make_float2(acc2[nt][2], acc2[nt][3]);
        }
    }
    __syncthreads();

    // ---- final reduce over 16 warps, divide by S, store ----
    {
        const int o = tid * 2;
        const int r = o >> 6, c = o & 63;
        float s0 = 0.f, s1 = 0.f;
        #pragma unroll
        for (int gg = 0; gg < 16; gg++) {
            const float2 v = *(const float2*)&redbuf[gg * 1024 + o];
            s0 += v.x; s1 += v.y;
        }
        const float inv = 1.0f / Srow[r];
        const int bb = bh >> 3, hh = bh & 7;
        *(float2*)&Og[((size_t)(bb * T_ + row0 + r)) * D_ + hh * 64 + c] =
            make_float2(s0 * inv, s1 * inv);
    }
}

// ---------------------------------------------------------------------------
extern "C" void kernel_launch(void* const* d_in, const int* in_sizes, int n_in,
                              void* d_out, int out_size) {
    const float* q  = (const float*)d_in[0];
    const float* k  = (const float*)d_in[1];
    const float* v  = (const float*)d_in[2];
    const float* Wq = (const float*)d_in[3];
    const float* bq = (const float*)d_in[4];
    const float* Wk = (const float*)d_in[5];
    const float* bk = (const float*)d_in[6];
    const float* Wv = (const float*)d_in[7];
    const float* bv = (const float*)d_in[8];
    const float* Wo = (const float*)d_in[9];
    const float* bo = (const float*)d_in[10];
    float* out = (float*)d_out;

    float *gQ, *gQlo, *gKT, *gV, *gO;
    cudaGetSymbolAddress((void**)&gQ, g_Q);
    cudaGetSymbolAddress((void**)&gQlo, g_Qlo);
    cudaGetSymbolAddress((void**)&gKT, g_KT);
    cudaGetSymbolAddress((void**)&gV, g_V);
    cudaGetSymbolAddress((void**)&gO, g_O);

    cudaFuncSetAttribute(attn_kernel, cudaFuncAttributeMaxDynamicSharedMemorySize,
                         ATTN_SMEM_BYTES);

    proj_kernel<<<dim3(32, 4, 3), 256>>>(q, k, v, Wq, bq, Wk, bk, Wv, bv,
                                         gQ, gQlo, gKT, gV);
    attn_kernel<<<dim3(128, 16), 512, ATTN_SMEM_BYTES>>>(gQ, gQlo, gKT, gV, gO);
    outproj_kernel<<<dim3(32, 4), 256>>>(gO, Wo, bo, out);
}

// round 11
// speedup vs baseline: 2.7516x; 1.0496x over previous
#include <cuda_runtime.h>
#include <cstdint>

#define B_  2
#define T_  2048
#define D_  512
#define H_  8
#define DK_ 64

__device__ float g_Q  [B_ * H_ * T_ * DK_];   // [bh][t][k] tf32 hi
__device__ float g_Qlo[B_ * H_ * T_ * DK_];   // [bh][t][k] residual
__device__ float g_KT [B_ * H_ * DK_ * T_];   // [bh][k][t] fp32
__device__ float g_V  [B_ * H_ * T_ * DK_];   // [bh][t][k] tf32-rounded
__device__ float g_O  [B_ * T_ * D_];

__device__ __forceinline__ float tf32_rna(float x) {
    uint32_t r;
    asm("cvt.rna.tf32.f32 %0, %1;" : "=r"(r) : "f"(x));
    return __uint_as_float(r);
}
__device__ __forceinline__ void mma_k4(float* d, float a0, float a1, float b0) {
    asm volatile(
        "mma.sync.aligned.m16n8k4.row.col.f32.tf32.tf32.f32 "
        "{%0,%1,%2,%3}, {%4,%5}, {%6}, {%0,%1,%2,%3};\n"
        : "+f"(d[0]), "+f"(d[1]), "+f"(d[2]), "+f"(d[3])
        : "r"(__float_as_uint(a0)), "r"(__float_as_uint(a1)),
          "r"(__float_as_uint(b0)));
}
__device__ __forceinline__ void mma_k8(float* d, float a0, float a1, float a2,
                                       float a3, float b0, float b1) {
    asm volatile(
        "mma.sync.aligned.m16n8k8.row.col.f32.tf32.tf32.f32 "
        "{%0,%1,%2,%3}, {%4,%5,%6,%7}, {%8,%9}, {%0,%1,%2,%3};\n"
        : "+f"(d[0]), "+f"(d[1]), "+f"(d[2]), "+f"(d[3])
        : "r"(__float_as_uint(a0)), "r"(__float_as_uint(a1)),
          "r"(__float_as_uint(a2)), "r"(__float_as_uint(a3)),
          "r"(__float_as_uint(b0)), "r"(__float_as_uint(b1)));
}

// ---------------------------------------------------------------------------
// Tensor-core projection GEMM: Y = X@W^T + bias, M=4096, N=K=512.
// 128x128 tile, 256 thr (8 warps, 2m x 4n), warp tile 64x32.
// mode 0 (Q): 3xTF32, write hi + lo, head layout
// mode 1 (K): 3xTF32, write fp32 transposed [bh][k][t]
// mode 2 (V): 1xTF32, write tf32-rounded, head layout
// Smem: As/Bs staged k-major, 32-k chunks, row stride 136 (conflict-free frags)
// ---------------------------------------------------------------------------
#define KSS 136

__global__ __launch_bounds__(256)
void tproj_kernel(const float* __restrict__ q, const float* __restrict__ k,
                  const float* __restrict__ v,
                  const float* __restrict__ Wq, const float* __restrict__ bq,
                  const float* __restrict__ Wk, const float* __restrict__ bk,
                  const float* __restrict__ Wv, const float* __restrict__ bv,
                  float* __restrict__ gQ, float* __restrict__ gQlo,
                  float* __restrict__ gKT, float* __restrict__ gV) {
    __shared__ float As[32 * KSS];
    __shared__ float Bs[32 * KSS];
    const int mode = blockIdx.z;
    const float* X; const float* W; const float* bias;
    if (mode == 0)      { X = q; W = Wq; bias = bq; }
    else if (mode == 1) { X = k; W = Wk; bias = bk; }
    else                { X = v; W = Wv; bias = bv; }

    const int tid = threadIdx.x;
    const int lane = tid & 31;
    const int gid = lane >> 2, tig = lane & 3;
    const int warp = tid >> 5;
    const int wm = warp >> 2, wn = warp & 3;
    const int m0 = blockIdx.x * 128, n0 = blockIdx.y * 128;

    const int lm  = tid & 127;          // staging row
    const int lk0 = (tid >> 7) * 2;     // staging k4 base (0 or 2)

    float acc[4][4][4] = {};            // [mt][nt][reg]

    for (int kc = 0; kc < 512; kc += 32) {
        __syncthreads();
        #pragma unroll
        for (int i = 0; i < 4; i++) {
            const int k4 = lk0 + (i & 1) + (i >> 1) * 4;   // covers 0..7
            const float4 xa = *(const float4*)&X[(size_t)(m0 + lm) * 512 + kc + k4 * 4];
            As[(k4 * 4 + 0) * KSS + lm] = xa.x;
            As[(k4 * 4 + 1) * KSS + lm] = xa.y;
            As[(k4 * 4 + 2) * KSS + lm] = xa.z;
            As[(k4 * 4 + 3) * KSS + lm] = xa.w;
            const float4 wb = *(const float4*)&W[(size_t)(n0 + lm) * 512 + kc + k4 * 4];
            Bs[(k4 * 4 + 0) * KSS + lm] = wb.x;
            Bs[(k4 * 4 + 1) * KSS + lm] = wb.y;
            Bs[(k4 * 4 + 2) * KSS + lm] = wb.z;
            Bs[(k4 * 4 + 3) * KSS + lm] = wb.w;
        }
        __syncthreads();
        #pragma unroll
        for (int ks = 0; ks < 32; ks += 8) {
            float bh0[4], bl0[4], bh1[4], bl1[4];
            #pragma unroll
            for (int nt = 0; nt < 4; nt++) {
                const int n = wn * 32 + nt * 8 + gid;
                const float b0 = Bs[(ks + tig) * KSS + n];
                const float b1 = Bs[(ks + tig + 4) * KSS + n];
                bh0[nt] = tf32_rna(b0); bl0[nt] = b0 - bh0[nt];
                bh1[nt] = tf32_rna(b1); bl1[nt] = b1 - bh1[nt];
            }
            #pragma unroll
            for (int mt = 0; mt < 4; mt++) {
                const int m = wm * 64 + mt * 16 + gid;
                const float a0 = As[(ks + tig) * KSS + m];
                const float a1 = As[(ks + tig) * KSS + m + 8];
                const float a2 = As[(ks + tig + 4) * KSS + m];
                const float a3 = As[(ks + tig + 4) * KSS + m + 8];
                const float a0h = tf32_rna(a0), a0l = a0 - a0h;
                const float a1h = tf32_rna(a1), a1l = a1 - a1h;
                const float a2h = tf32_rna(a2), a2l = a2 - a2h;
                const float a3h = tf32_rna(a3), a3l = a3 - a3h;
                #pragma unroll
                for (int nt = 0; nt < 4; nt++) {
                    mma_k8(acc[mt][nt], a0h, a1h, a2h, a3h, bh0[nt], bh1[nt]);
                    if (mode != 2) {
                        mma_k8(acc[mt][nt], a0h, a1h, a2h, a3h, bl0[nt], bl1[nt]);
                        mma_k8(acc[mt][nt], a0l, a1l, a2l, a3l, bh0[nt], bh1[nt]);
                    }
                }
            }
        }
    }

    // epilogue: c0,c1 = (row gid, cols 2tig,2tig+1); c2,c3 = (row gid+8)
    #pragma unroll
    for (int mt = 0; mt < 4; mt++) {
        #pragma unroll
        for (int nt = 0; nt < 4; nt++) {
            const int mr0 = m0 + wm * 64 + mt * 16 + gid;
            const int mr1 = mr0 + 8;
            const int col = n0 + wn * 32 + nt * 8 + tig * 2;
            const float bs0 = bias[col], bs1 = bias[col + 1];
            const float vals[4] = {acc[mt][nt][0] + bs0, acc[mt][nt][1] + bs1,
                                   acc[mt][nt][2] + bs0, acc[mt][nt][3] + bs1};
            const int rows[2] = {mr0, mr1};
            #pragma unroll
            for (int rr = 0; rr < 2; rr++) {
                const int m = rows[rr];
                const int b = m >> 11, t = m & (T_ - 1);
                #pragma unroll
                for (int cc = 0; cc < 2; cc++) {
                    const int c = col + cc;
                    const int h = c >> 6, d = c & 63;
                    const float val = vals[rr * 2 + cc];
                    if (mode == 1) {
                        gKT[((size_t)((b * H_ + h) * DK_ + d)) * T_ + t] = val;
                    } else {
                        const size_t base =
                            (((size_t)(b * H_ + h)) * T_ + t) * DK_ + d;
                        if (mode == 0) {
                            const float hi = tf32_rna(val);
                            gQ[base] = hi;
                            gQlo[base] = val - hi;
                        } else {
                            gV[base] = tf32_rna(val);
                        }
                    }
                }
            }
        }
    }
}

// ---------------------------------------------------------------------------
// Out-projection: SIMT fp32 GEMM (unchanged; 45 us, full precision).
// ---------------------------------------------------------------------------
__global__ __launch_bounds__(256)
void outproj_kernel(const float* __restrict__ X, const float* __restrict__ W,
                    const float* __restrict__ bias, float* __restrict__ Y) {
    __shared__ float Xs[16 * 132];
    __shared__ float Ws[16 * 132];
    const int tid = threadIdx.x;
    const int rg = tid >> 4, cg = tid & 15;
    const int m0 = blockIdx.x * 128, n0 = blockIdx.y * 128;
    const int mm0 = tid >> 2,         kk40 = tid & 3;
    const int mm1 = (tid + 256) >> 2, kk41 = (tid + 256) & 3;

    float acc[8][8] = {};
    float4 xr0, xr1, wr0, wr1;
    xr0 = *(const float4*)&X[(size_t)(m0 + mm0) * 512 + kk40 * 4];
    xr1 = *(const float4*)&X[(size_t)(m0 + mm1) * 512 + kk41 * 4];
    wr0 = *(const float4*)&W[(size_t)(n0 + mm0) * 512 + kk40 * 4];
    wr1 = *(const float4*)&W[(size_t)(n0 + mm1) * 512 + kk41 * 4];

    for (int kt = 0; kt < 512; kt += 16) {
        __syncthreads();
        Xs[(kk40 * 4 + 0) * 132 + mm0] = xr0.x;
        Xs[(kk40 * 4 + 1) * 132 + mm0] = xr0.y;
        Xs[(kk40 * 4 + 2) * 132 + mm0] = xr0.z;
        Xs[(kk40 * 4 + 3) * 132 + mm0] = xr0.w;
        Xs[(kk41 * 4 + 0) * 132 + mm1] = xr1.x;
        Xs[(kk41 * 4 + 1) * 132 + mm1] = xr1.y;
        Xs[(kk41 * 4 + 2) * 132 + mm1] = xr1.z;
        Xs[(kk41 * 4 + 3) * 132 + mm1] = xr1.w;
        Ws[(kk40 * 4 + 0) * 132 + mm0] = wr0.x;
        Ws[(kk40 * 4 + 1) * 132 + mm0] = wr0.y;
        Ws[(kk40 * 4 + 2) * 132 + mm0] = wr0.z;
        Ws[(kk40 * 4 + 3) * 132 + mm0] = wr0.w;
        Ws[(kk41 * 4 + 0) * 132 + mm1] = wr1.x;
        Ws[(kk41 * 4 + 1) * 132 + mm1] = wr1.y;
        Ws[(kk41 * 4 + 2) * 132 + mm1] = wr1.z;
        Ws[(kk41 * 4 + 3) * 132 + mm1] = wr1.w;
        __syncthreads();
        if (kt + 16 < 512) {
            const int kn = kt + 16;
            xr0 = *(const float4*)&X[(size_t)(m0 + mm0) * 512 + kn + kk40 * 4];
            xr1 = *(const float4*)&X[(size_t)(m0 + mm1) * 512 + kn + kk41 * 4];
            wr0 = *(const float4*)&W[(size_t)(n0 + mm0) * 512 + kn + kk40 * 4];
            wr1 = *(const float4*)&W[(size_t)(n0 + mm1) * 512 + kn + kk41 * 4];
        }
        #pragma unroll
        for (int kk = 0; kk < 16; kk++) {
            const float4 a0 = *(const float4*)&Xs[kk * 132 + rg * 4];
            const float4 a1 = *(const float4*)&Xs[kk * 132 + 64 + rg * 4];
            const float4 b0 = *(const float4*)&Ws[kk * 132 + cg * 4];
            const float4 b1 = *(const float4*)&Ws[kk * 132 + 64 + cg * 4];
            const float av[8] = {a0.x, a0.y, a0.z, a0.w, a1.x, a1.y, a1.z, a1.w};
            const float bv[8] = {b0.x, b0.y, b0.z, b0.w, b1.x, b1.y, b1.z, b1.w};
            #pragma unroll
            for (int i = 0; i < 8; i++)
                #pragma unroll
                for (int j = 0; j < 8; j++)
                    acc[i][j] = fmaf(av[i], bv[j], acc[i][j]);
        }
    }

    const float4 bb0 = *(const float4*)&bias[n0 + cg * 4];
    const float4 bb1 = *(const float4*)&bias[n0 + 64 + cg * 4];
    #pragma unroll
    for (int ih = 0; ih < 2; ih++) {
        #pragma unroll
        for (int i = 0; i < 4; i++) {
            const int m = m0 + ih * 64 + rg * 4 + i;
            float4 o0, o1;
            o0.x = acc[ih * 4 + i][0] + bb0.x;
            o0.y = acc[ih * 4 + i][1] + bb0.y;
            o0.z = acc[ih * 4 + i][2] + bb0.z;
            o0.w = acc[ih * 4 + i][3] + bb0.w;
            o1.x = acc[ih * 4 + i][4] + bb1.x;
            o1.y = acc[ih * 4 + i][5] + bb1.y;
            o1.z = acc[ih * 4 + i][6] + bb1.z;
            o1.w = acc[ih * 4 + i][7] + bb1.w;
            *(float4*)&Y[(size_t)m * 512 + n0 + cg * 4] = o0;
            *(float4*)&Y[(size_t)m * 512 + n0 + 64 + cg * 4] = o1;
        }
    }
}

// ---------------------------------------------------------------------------
// Attention (tf32 tensor cores): 16 rows/block, 512 threads, 16 warps.
// 3xTF32 scores with K register-prefetch + barrier-free pass 2.
// Smem floats: P[16][2052] @0 | redbuf[16][1024] @32832 | Qs2 f2[64][17]
// @49216 | Srow[16] @51392  => 205,632 B
// ---------------------------------------------------------------------------
#define PST      2052
#define RED_OFF  32832
#define QS_OFF   49216
#define SROW_OFF 51392
#define ATTN_SMEM_BYTES ((SROW_OFF + 16) * 4)

__global__ __launch_bounds__(512)
void attn_kernel(const float* __restrict__ Qh, const float* __restrict__ Qlo,
                 const float* __restrict__ KT, const float* __restrict__ Vh,
                 float* __restrict__ Og) {
    extern __shared__ float sm[];
    float*  P      = sm;
    float*  redbuf = sm + RED_OFF;
    float2* Qs2    = (float2*)(sm + QS_OFF);   // [k][r] stride 17
    float*  Srow   = sm + SROW_OFF;

    const int tid  = threadIdx.x;
    const int w    = tid >> 5;
    const int lane = tid & 31;
    const int gid  = lane >> 2;     // 0..7
    const int tig  = lane & 3;      // 0..3
    const int bh   = blockIdx.y;
    const int row0 = blockIdx.x * 16;

    const float* Qb  = Qh  + ((size_t)bh * T_ + row0) * DK_;
    const float* Qlb = Qlo + ((size_t)bh * T_ + row0) * DK_;
    const float* KTb = KT  + (size_t)bh * DK_ * T_;
    const float* Vb  = Vh  + (size_t)bh * T_ * DK_;

    if (tid < 256) {
        const int r = tid & 15, k4 = tid >> 4;
        const float4 h4 = *(const float4*)&Qb [(size_t)r * DK_ + k4 * 4];
        const float4 l4 = *(const float4*)&Qlb[(size_t)r * DK_ + k4 * 4];
        Qs2[(k4 * 4 + 0) * 17 + r] = make_float2(h4.x, l4.x);
        Qs2[(k4 * 4 + 1) * 17 + r] = make_float2(h4.y, l4.y);
        Qs2[(k4 * 4 + 2) * 17 + r] = make_float2(h4.z, l4.z);
        Qs2[(k4 * 4 + 3) * 17 + r] = make_float2(h4.w, l4.w);
    }
    __syncthreads();

    // ---- pass 1: 3xTF32 scores; K fp32, hi/lo on the fly, reg prefetch ----
    {
        float acc[16][4] = {};
        const float* KTl = KTb + (size_t)tig * T_ + w * 128 + gid;

        float bk[16];
        #pragma unroll
        for (int nt = 0; nt < 16; nt++) bk[nt] = KTl[nt * 8];

        for (int ksc = 0; ksc < 16; ksc++) {
            const float2 qa = Qs2[(ksc * 4 + tig) * 17 + gid];      // row gid
            const float2 qb = Qs2[(ksc * 4 + tig) * 17 + gid + 8];  // row gid+8
            float bkn[16];
            if (ksc < 15) {
                const float* Kn = KTl + (size_t)((ksc + 1) * 4) * T_;
                #pragma unroll
                for (int nt = 0; nt < 16; nt++) bkn[nt] = Kn[nt * 8];
            }
            #pragma unroll
            for (int nt = 0; nt < 16; nt++) {
                float* a = acc[nt];
                const float hi = tf32_rna(bk[nt]);
                const float lo = bk[nt] - hi;
                mma_k4(a, qa.x, qb.x, hi);   // qhi * khi
                mma_k4(a, qa.x, qb.x, lo);   // qhi * klo
                mma_k4(a, qa.y, qb.y, hi);   // qlo * khi
            }
            #pragma unroll
            for (int nt = 0; nt < 16; nt++) bk[nt] = bkn[nt];
        }
        #pragma unroll
        for (int nt = 0; nt < 16; nt++) {
            const int col = w * 128 + nt * 8 + tig * 2;
            *(float2*)&P[gid * PST + col]       = make_float2(acc[nt][0], acc[nt][1]);
            *(float2*)&P[(gid + 8) * PST + col] = make_float2(acc[nt][2], acc[nt][3]);
        }
    }
    __syncthreads();

    // ---- sweep: one warp per row: max, exp+sum, threshold+rna ----
    {
        float4* Pr = (float4*)(P + w * PST);
        float m = -1e30f;
        #pragma unroll 4
        for (int j = lane; j < 512; j += 32) {
            const float4 v = Pr[j];
            m = fmaxf(m, fmaxf(fmaxf(v.x, v.y), fmaxf(v.z, v.w)));
        }
        #pragma unroll
        for (int o = 16; o; o >>= 1) m = fmaxf(m, __shfl_xor_sync(0xffffffffu, m, o));
        float s = 0.f;
        #pragma unroll 4
        for (int j = lane; j < 512; j += 32) {
            float4 v = Pr[j];
            v.x = __expf(v.x - m); v.y = __expf(v.y - m);
            v.z = __expf(v.z - m); v.w = __expf(v.w - m);
            Pr[j] = v;
            s += (v.x + v.y) + (v.z + v.w);
        }
        #pragma unroll
        for (int o = 16; o; o >>= 1) s += __shfl_xor_sync(0xffffffffu, s, o);
        const float thr = s * (1.0f / 2048.0f);
        #pragma unroll 4
        for (int j = lane; j < 512; j += 32) {
            float4 v = Pr[j];
            v.x = (v.x > thr) ? tf32_rna(v.x) : 0.f;
            v.y = (v.y > thr) ? tf32_rna(v.y) : 0.f;
            v.z = (v.z > thr) ? tf32_rna(v.z) : 0.f;
            v.w = (v.w > thr) ? tf32_rna(v.w) : 0.f;
            Pr[j] = v;
        }
        if (lane == 0) Srow[w] = s;
    }
    __syncthreads();

    // ---- pass 2: out = P_thr @ V; V fragments direct from global ----
    {
        float acc2[8][4] = {};
        #pragma unroll 2
        for (int vt = 0; vt < 16; vt++) {
            const int kg = vt * 128 + w * 8 + tig;
            const float a0 = P[gid * PST + kg];
            const float a1 = P[(gid + 8) * PST + kg];
            const float a2 = P[gid * PST + kg + 4];
            const float a3 = P[(gid + 8) * PST + kg + 4];
            const float* Vr0 = Vb + (size_t)kg * DK_ + gid;
            const float* Vr1 = Vb + (size_t)(kg + 4) * DK_ + gid;
            float b0[8], b1[8];
            #pragma unroll
            for (int nt = 0; nt < 8; nt++) {
                b0[nt] = Vr0[nt * 8];
                b1[nt] = Vr1[nt * 8];
            }
            #pragma unroll
            for (int nt = 0; nt < 8; nt++)
                mma_k8(acc2[nt], a0, a1, a2, a3, b0[nt], b1[nt]);
        }
        #pragma unroll
        for (int nt = 0; nt < 8; nt++) {
            const int col = nt * 8 + tig * 2;
            *(float2*)&redbuf[w * 1024 + gid * 64 + col] =
                make_float2(acc2[nt][0], acc2[nt][1]);
            *(float2*)&redbuf[w * 1024 + (gid + 8) * 64 + col] =
                make_float2(acc2[nt][2], acc2[nt][3]);
        }
    }
    __syncthreads();

    // ---- final reduce over 16 warps, divide by S, store ----
    {
        const int o = tid * 2;
        const int r = o >> 6, c = o & 63;
        float s0 = 0.f, s1 = 0.f;
        #pragma unroll
        for (int gg = 0; gg < 16; gg++) {
            const float2 v = *(const float2*)&redbuf[gg * 1024 + o];
            s0 += v.x; s1 += v.y;
        }
        const float inv = 1.0f / Srow[r];
        const int bb = bh >> 3, hh = bh & 7;
        *(float2*)&Og[((size_t)(bb * T_ + row0 + r)) * D_ + hh * 64 + c] =
            make_float2(s0 * inv, s1 * inv);
    }
}

// ---------------------------------------------------------------------------
extern "C" void kernel_launch(void* const* d_in, const int* in_sizes, int n_in,
                              void* d_out, int out_size) {
    const float* q  = (const float*)d_in[0];
    const float* k  = (const float*)d_in[1];
    const float* v  = (const float*)d_in[2];
    const float* Wq = (const float*)d_in[3];
    const float* bq = (const float*)d_in[4];
    const float* Wk = (const float*)d_in[5];
    const float* bk = (const float*)d_in[6];
    const float* Wv = (const float*)d_in[7];
    const float* bv = (const float*)d_in[8];
    const float* Wo = (const float*)d_in[9];
    const float* bo = (const float*)d_in[10];
    float* out = (float*)d_out;

    float *gQ, *gQlo, *gKT, *gV, *gO;
    cudaGetSymbolAddress((void**)&gQ, g_Q);
    cudaGetSymbolAddress((void**)&gQlo, g_Qlo);
    cudaGetSymbolAddress((void**)&gKT, g_KT);
    cudaGetSymbolAddress((void**)&gV, g_V);
    cudaGetSymbolAddress((void**)&gO, g_O);

    cudaFuncSetAttribute(attn_kernel, cudaFuncAttributeMaxDynamicSharedMemorySize,
                         ATTN_SMEM_BYTES);

    tproj_kernel<<<dim3(32, 4, 3), 256>>>(q, k, v, Wq, bq, Wk, bk, Wv, bv,
                                          gQ, gQlo, gKT, gV);
    attn_kernel<<<dim3(128, 16), 512, ATTN_SMEM_BYTES>>>(gQ, gQlo, gKT, gV, gO);
    outproj_kernel<<<dim3(32, 4), 256>>>(gO, Wo, bo, out);
}

// round 12
// speedup vs baseline: 2.7770x; 1.0092x over previous
#include <cuda_runtime.h>
#include <cstdint>

#define B_  2
#define T_  2048
#define D_  512
#define H_  8
#define DK_ 64

__device__ float g_Q  [B_ * H_ * T_ * DK_];   // [bh][t][k] tf32 hi
__device__ float g_Qlo[B_ * H_ * T_ * DK_];   // [bh][t][k] residual
__device__ float g_KT [B_ * H_ * DK_ * T_];   // [bh][k][t] fp32
__device__ float g_V  [B_ * H_ * T_ * DK_];   // [bh][t][k] tf32-rounded
__device__ float g_O  [B_ * T_ * D_];

__device__ __forceinline__ float tf32_rna(float x) {
    uint32_t r;
    asm("cvt.rna.tf32.f32 %0, %1;" : "=r"(r) : "f"(x));
    return __uint_as_float(r);
}
__device__ __forceinline__ void mma_k4(float* d, float a0, float a1, float b0) {
    asm volatile(
        "mma.sync.aligned.m16n8k4.row.col.f32.tf32.tf32.f32 "
        "{%0,%1,%2,%3}, {%4,%5}, {%6}, {%0,%1,%2,%3};\n"
        : "+f"(d[0]), "+f"(d[1]), "+f"(d[2]), "+f"(d[3])
        : "r"(__float_as_uint(a0)), "r"(__float_as_uint(a1)),
          "r"(__float_as_uint(b0)));
}
__device__ __forceinline__ void mma_k8(float* d, float a0, float a1, float a2,
                                       float a3, float b0, float b1) {
    asm volatile(
        "mma.sync.aligned.m16n8k8.row.col.f32.tf32.tf32.f32 "
        "{%0,%1,%2,%3}, {%4,%5,%6,%7}, {%8,%9}, {%0,%1,%2,%3};\n"
        : "+f"(d[0]), "+f"(d[1]), "+f"(d[2]), "+f"(d[3])
        : "r"(__float_as_uint(a0)), "r"(__float_as_uint(a1)),
          "r"(__float_as_uint(a2)), "r"(__float_as_uint(a3)),
          "r"(__float_as_uint(b0)), "r"(__float_as_uint(b1)));
}

// ---------------------------------------------------------------------------
// Tensor-core projection GEMM: Y = X@W^T + bias, M=4096, N=K=512.
// 128x128 tile, 256 thr (8 warps, 2m x 4n), warp tile 64x32. 3xTF32 all modes.
// mode 0 (Q): write hi + lo, head layout
// mode 1 (K): write fp32 transposed [bh][k][t]
// mode 2 (V): write tf32-rounded, head layout
// ---------------------------------------------------------------------------
#define KSS 136

__global__ __launch_bounds__(256)
void tproj_kernel(const float* __restrict__ q, const float* __restrict__ k,
                  const float* __restrict__ v,
                  const float* __restrict__ Wq, const float* __restrict__ bq,
                  const float* __restrict__ Wk, const float* __restrict__ bk,
                  const float* __restrict__ Wv, const float* __restrict__ bv,
                  float* __restrict__ gQ, float* __restrict__ gQlo,
                  float* __restrict__ gKT, float* __restrict__ gV) {
    __shared__ float As[32 * KSS];
    __shared__ float Bs[32 * KSS];
    const int mode = blockIdx.z;
    const float* X; const float* W; const float* bias;
    if (mode == 0)      { X = q; W = Wq; bias = bq; }
    else if (mode == 1) { X = k; W = Wk; bias = bk; }
    else                { X = v; W = Wv; bias = bv; }

    const int tid = threadIdx.x;
    const int lane = tid & 31;
    const int gid = lane >> 2, tig = lane & 3;
    const int warp = tid >> 5;
    const int wm = warp >> 2, wn = warp & 3;
    const int m0 = blockIdx.x * 128, n0 = blockIdx.y * 128;

    const int lm  = tid & 127;
    const int lk0 = (tid >> 7) * 2;

    float acc[4][4][4] = {};

    for (int kc = 0; kc < 512; kc += 32) {
        __syncthreads();
        #pragma unroll
        for (int i = 0; i < 4; i++) {
            const int k4 = lk0 + (i & 1) + (i >> 1) * 4;
            const float4 xa = *(const float4*)&X[(size_t)(m0 + lm) * 512 + kc + k4 * 4];
            As[(k4 * 4 + 0) * KSS + lm] = xa.x;
            As[(k4 * 4 + 1) * KSS + lm] = xa.y;
            As[(k4 * 4 + 2) * KSS + lm] = xa.z;
            As[(k4 * 4 + 3) * KSS + lm] = xa.w;
            const float4 wb = *(const float4*)&W[(size_t)(n0 + lm) * 512 + kc + k4 * 4];
            Bs[(k4 * 4 + 0) * KSS + lm] = wb.x;
            Bs[(k4 * 4 + 1) * KSS + lm] = wb.y;
            Bs[(k4 * 4 + 2) * KSS + lm] = wb.z;
            Bs[(k4 * 4 + 3) * KSS + lm] = wb.w;
        }
        __syncthreads();
        #pragma unroll
        for (int ks = 0; ks < 32; ks += 8) {
            float bh0[4], bl0[4], bh1[4], bl1[4];
            #pragma unroll
            for (int nt = 0; nt < 4; nt++) {
                const int n = wn * 32 + nt * 8 + gid;
                const float b0 = Bs[(ks + tig) * KSS + n];
                const float b1 = Bs[(ks + tig + 4) * KSS + n];
                bh0[nt] = tf32_rna(b0); bl0[nt] = b0 - bh0[nt];
                bh1[nt] = tf32_rna(b1); bl1[nt] = b1 - bh1[nt];
            }
            #pragma unroll
            for (int mt = 0; mt < 4; mt++) {
                const int m = wm * 64 + mt * 16 + gid;
                const float a0 = As[(ks + tig) * KSS + m];
                const float a1 = As[(ks + tig) * KSS + m + 8];
                const float a2 = As[(ks + tig + 4) * KSS + m];
                const float a3 = As[(ks + tig + 4) * KSS + m + 8];
                const float a0h = tf32_rna(a0), a0l = a0 - a0h;
                const float a1h = tf32_rna(a1), a1l = a1 - a1h;
                const float a2h = tf32_rna(a2), a2l = a2 - a2h;
                const float a3h = tf32_rna(a3), a3l = a3 - a3h;
                #pragma unroll
                for (int nt = 0; nt < 4; nt++) {
                    mma_k8(acc[mt][nt], a0h, a1h, a2h, a3h, bh0[nt], bh1[nt]);
                    mma_k8(acc[mt][nt], a0h, a1h, a2h, a3h, bl0[nt], bl1[nt]);
                    mma_k8(acc[mt][nt], a0l, a1l, a2l, a3l, bh0[nt], bh1[nt]);
                }
            }
        }
    }

    #pragma unroll
    for (int mt = 0; mt < 4; mt++) {
        #pragma unroll
        for (int nt = 0; nt < 4; nt++) {
            const int mr0 = m0 + wm * 64 + mt * 16 + gid;
            const int mr1 = mr0 + 8;
            const int col = n0 + wn * 32 + nt * 8 + tig * 2;
            const float bs0 = bias[col], bs1 = bias[col + 1];
            const float vals[4] = {acc[mt][nt][0] + bs0, acc[mt][nt][1] + bs1,
                                   acc[mt][nt][2] + bs0, acc[mt][nt][3] + bs1};
            const int rows[2] = {mr0, mr1};
            #pragma unroll
            for (int rr = 0; rr < 2; rr++) {
                const int m = rows[rr];
                const int b = m >> 11, t = m & (T_ - 1);
                #pragma unroll
                for (int cc = 0; cc < 2; cc++) {
                    const int c = col + cc;
                    const int h = c >> 6, d = c & 63;
                    const float val = vals[rr * 2 + cc];
                    if (mode == 1) {
                        gKT[((size_t)((b * H_ + h) * DK_ + d)) * T_ + t] = val;
                    } else {
                        const size_t base =
                            (((size_t)(b * H_ + h)) * T_ + t) * DK_ + d;
                        if (mode == 0) {
                            const float hi = tf32_rna(val);
                            gQ[base] = hi;
                            gQlo[base] = val - hi;
                        } else {
                            gV[base] = tf32_rna(val);
                        }
                    }
                }
            }
        }
    }
}

// ---------------------------------------------------------------------------
// Out-projection: SIMT fp32 GEMM (full precision).
// ---------------------------------------------------------------------------
__global__ __launch_bounds__(256)
void outproj_kernel(const float* __restrict__ X, const float* __restrict__ W,
                    const float* __restrict__ bias, float* __restrict__ Y) {
    __shared__ float Xs[16 * 132];
    __shared__ float Ws[16 * 132];
    const int tid = threadIdx.x;
    const int rg = tid >> 4, cg = tid & 15;
    const int m0 = blockIdx.x * 128, n0 = blockIdx.y * 128;
    const int mm0 = tid >> 2,         kk40 = tid & 3;
    const int mm1 = (tid + 256) >> 2, kk41 = (tid + 256) & 3;

    float acc[8][8] = {};
    float4 xr0, xr1, wr0, wr1;
    xr0 = *(const float4*)&X[(size_t)(m0 + mm0) * 512 + kk40 * 4];
    xr1 = *(const float4*)&X[(size_t)(m0 + mm1) * 512 + kk41 * 4];
    wr0 = *(const float4*)&W[(size_t)(n0 + mm0) * 512 + kk40 * 4];
    wr1 = *(const float4*)&W[(size_t)(n0 + mm1) * 512 + kk41 * 4];

    for (int kt = 0; kt < 512; kt += 16) {
        __syncthreads();
        Xs[(kk40 * 4 + 0) * 132 + mm0] = xr0.x;
        Xs[(kk40 * 4 + 1) * 132 + mm0] = xr0.y;
        Xs[(kk40 * 4 + 2) * 132 + mm0] = xr0.z;
        Xs[(kk40 * 4 + 3) * 132 + mm0] = xr0.w;
        Xs[(kk41 * 4 + 0) * 132 + mm1] = xr1.x;
        Xs[(kk41 * 4 + 1) * 132 + mm1] = xr1.y;
        Xs[(kk41 * 4 + 2) * 132 + mm1] = xr1.z;
        Xs[(kk41 * 4 + 3) * 132 + mm1] = xr1.w;
        Ws[(kk40 * 4 + 0) * 132 + mm0] = wr0.x;
        Ws[(kk40 * 4 + 1) * 132 + mm0] = wr0.y;
        Ws[(kk40 * 4 + 2) * 132 + mm0] = wr0.z;
        Ws[(kk40 * 4 + 3) * 132 + mm0] = wr0.w;
        Ws[(kk41 * 4 + 0) * 132 + mm1] = wr1.x;
        Ws[(kk41 * 4 + 1) * 132 + mm1] = wr1.y;
        Ws[(kk41 * 4 + 2) * 132 + mm1] = wr1.z;
        Ws[(kk41 * 4 + 3) * 132 + mm1] = wr1.w;
        __syncthreads();
        if (kt + 16 < 512) {
            const int kn = kt + 16;
            xr0 = *(const float4*)&X[(size_t)(m0 + mm0) * 512 + kn + kk40 * 4];
            xr1 = *(const float4*)&X[(size_t)(m0 + mm1) * 512 + kn + kk41 * 4];
            wr0 = *(const float4*)&W[(size_t)(n0 + mm0) * 512 + kn + kk40 * 4];
            wr1 = *(const float4*)&W[(size_t)(n0 + mm1) * 512 + kn + kk41 * 4];
        }
        #pragma unroll
        for (int kk = 0; kk < 16; kk++) {
            const float4 a0 = *(const float4*)&Xs[kk * 132 + rg * 4];
            const float4 a1 = *(const float4*)&Xs[kk * 132 + 64 + rg * 4];
            const float4 b0 = *(const float4*)&Ws[kk * 132 + cg * 4];
            const float4 b1 = *(const float4*)&Ws[kk * 132 + 64 + cg * 4];
            const float av[8] = {a0.x, a0.y, a0.z, a0.w, a1.x, a1.y, a1.z, a1.w};
            const float bv[8] = {b0.x, b0.y, b0.z, b0.w, b1.x, b1.y, b1.z, b1.w};
            #pragma unroll
            for (int i = 0; i < 8; i++)
                #pragma unroll
                for (int j = 0; j < 8; j++)
                    acc[i][j] = fmaf(av[i], bv[j], acc[i][j]);
        }
    }

    const float4 bb0 = *(const float4*)&bias[n0 + cg * 4];
    const float4 bb1 = *(const float4*)&bias[n0 + 64 + cg * 4];
    #pragma unroll
    for (int ih = 0; ih < 2; ih++) {
        #pragma unroll
        for (int i = 0; i < 4; i++) {
            const int m = m0 + ih * 64 + rg * 4 + i;
            float4 o0, o1;
            o0.x = acc[ih * 4 + i][0] + bb0.x;
            o0.y = acc[ih * 4 + i][1] + bb0.y;
            o0.z = acc[ih * 4 + i][2] + bb0.z;
            o0.w = acc[ih * 4 + i][3] + bb0.w;
            o1.x = acc[ih * 4 + i][4] + bb1.x;
            o1.y = acc[ih * 4 + i][5] + bb1.y;
            o1.z = acc[ih * 4 + i][6] + bb1.z;
            o1.w = acc[ih * 4 + i][7] + bb1.w;
            *(float4*)&Y[(size_t)m * 512 + n0 + cg * 4] = o0;
            *(float4*)&Y[(size_t)m * 512 + n0 + 64 + cg * 4] = o1;
        }
    }
}

// ---------------------------------------------------------------------------
// Attention: 16 rows/block, 512 threads, 16 warps. P stays in REGISTERS.
// Warp w owns score cols [w*128, +128) for all 16 rows (acc[16][4]).
// Reductions via tig-shfl + 16x16 smem partials. Pass 2 shuffles acc into
// m16n8k8 A-fragments and multiplies against global-V fragments.
// Smem floats: Qs2 f2[64][17] @0 (2176) | pm @2176 (256) | ps @2432 (256) |
// Srow @2688 (16) | redbuf @2704 (16384)  => 19088 floats = 76,352 B
// ---------------------------------------------------------------------------
#define QS_OFF   0
#define PM_OFF   2176
#define PS_OFF   2432
#define SROW_OFF 2688
#define RED_OFF  2704
#define ATTN_SMEM_BYTES ((RED_OFF + 16384) * 4)

__global__ __launch_bounds__(512)
void attn_kernel(const float* __restrict__ Qh, const float* __restrict__ Qlo,
                 const float* __restrict__ KT, const float* __restrict__ Vh,
                 float* __restrict__ Og) {
    extern __shared__ float sm[];
    float2* Qs2    = (float2*)(sm + QS_OFF);   // [k][r] stride 17
    float*  pm     = sm + PM_OFF;              // [row][warp]
    float*  ps     = sm + PS_OFF;
    float*  Srow   = sm + SROW_OFF;
    float*  redbuf = sm + RED_OFF;

    const int tid  = threadIdx.x;
    const int w    = tid >> 5;
    const int lane = tid & 31;
    const int gid  = lane >> 2;     // 0..7
    const int tig  = lane & 3;      // 0..3
    const int bh   = blockIdx.y;
    const int row0 = blockIdx.x * 16;

    const float* Qb  = Qh  + ((size_t)bh * T_ + row0) * DK_;
    const float* Qlb = Qlo + ((size_t)bh * T_ + row0) * DK_;
    const float* KTb = KT  + (size_t)bh * DK_ * T_;
    const float* Vb  = Vh  + (size_t)bh * T_ * DK_;

    if (tid < 256) {
        const int r = tid & 15, k4 = tid >> 4;
        const float4 h4 = *(const float4*)&Qb [(size_t)r * DK_ + k4 * 4];
        const float4 l4 = *(const float4*)&Qlb[(size_t)r * DK_ + k4 * 4];
        Qs2[(k4 * 4 + 0) * 17 + r] = make_float2(h4.x, l4.x);
        Qs2[(k4 * 4 + 1) * 17 + r] = make_float2(h4.y, l4.y);
        Qs2[(k4 * 4 + 2) * 17 + r] = make_float2(h4.z, l4.z);
        Qs2[(k4 * 4 + 3) * 17 + r] = make_float2(h4.w, l4.w);
    }
    __syncthreads();

    // ---- pass 1: 3xTF32 scores into registers (K prefetched) ----
    float acc[16][4];
    #pragma unroll
    for (int nt = 0; nt < 16; nt++)
        #pragma unroll
        for (int j = 0; j < 4; j++) acc[nt][j] = 0.f;
    {
        const float* KTl = KTb + (size_t)tig * T_ + w * 128 + gid;
        float bk[16];
        #pragma unroll
        for (int nt = 0; nt < 16; nt++) bk[nt] = KTl[nt * 8];

        for (int ksc = 0; ksc < 16; ksc++) {
            const float2 qa = Qs2[(ksc * 4 + tig) * 17 + gid];
            const float2 qb = Qs2[(ksc * 4 + tig) * 17 + gid + 8];
            float bkn[16];
            if (ksc < 15) {
                const float* Kn = KTl + (size_t)((ksc + 1) * 4) * T_;
                #pragma unroll
                for (int nt = 0; nt < 16; nt++) bkn[nt] = Kn[nt * 8];
            }
            #pragma unroll
            for (int nt = 0; nt < 16; nt++) {
                float* a = acc[nt];
                const float hi = tf32_rna(bk[nt]);
                const float lo = bk[nt] - hi;
                mma_k4(a, qa.x, qb.x, hi);   // qhi * khi
                mma_k4(a, qa.x, qb.x, lo);   // qhi * klo
                mma_k4(a, qa.y, qb.y, hi);   // qlo * khi
            }
            #pragma unroll
            for (int nt = 0; nt < 16; nt++) bk[nt] = bkn[nt];
        }
    }

    // ---- row max (in-register + tig-shfl + cross-warp partials) ----
    {
        float m0 = -1e30f, m1 = -1e30f;
        #pragma unroll
        for (int nt = 0; nt < 16; nt++) {
            m0 = fmaxf(m0, fmaxf(acc[nt][0], acc[nt][1]));
            m1 = fmaxf(m1, fmaxf(acc[nt][2], acc[nt][3]));
        }
        m0 = fmaxf(m0, __shfl_xor_sync(0xffffffffu, m0, 1));
        m0 = fmaxf(m0, __shfl_xor_sync(0xffffffffu, m0, 2));
        m1 = fmaxf(m1, __shfl_xor_sync(0xffffffffu, m1, 1));
        m1 = fmaxf(m1, __shfl_xor_sync(0xffffffffu, m1, 2));
        if (tig == 0) {
            pm[gid * 16 + w]       = m0;
            pm[(gid + 8) * 16 + w] = m1;
        }
    }
    __syncthreads();
    float M0 = -1e30f, M1 = -1e30f;
    #pragma unroll
    for (int i = 0; i < 16; i++) {
        M0 = fmaxf(M0, pm[gid * 16 + i]);
        M1 = fmaxf(M1, pm[(gid + 8) * 16 + i]);
    }

    // ---- exp + row sum ----
    {
        float s0 = 0.f, s1 = 0.f;
        #pragma unroll
        for (int nt = 0; nt < 16; nt++) {
            acc[nt][0] = __expf(acc[nt][0] - M0);
            acc[nt][1] = __expf(acc[nt][1] - M0);
            acc[nt][2] = __expf(acc[nt][2] - M1);
            acc[nt][3] = __expf(acc[nt][3] - M1);
            s0 += acc[nt][0] + acc[nt][1];
            s1 += acc[nt][2] + acc[nt][3];
        }
        s0 += __shfl_xor_sync(0xffffffffu, s0, 1);
        s0 += __shfl_xor_sync(0xffffffffu, s0, 2);
        s1 += __shfl_xor_sync(0xffffffffu, s1, 1);
        s1 += __shfl_xor_sync(0xffffffffu, s1, 2);
        if (tig == 0) {
            ps[gid * 16 + w]       = s0;
            ps[(gid + 8) * 16 + w] = s1;
        }
    }
    __syncthreads();
    {
        float S0 = 0.f, S1 = 0.f;
        #pragma unroll
        for (int i = 0; i < 16; i++) {
            S0 += ps[gid * 16 + i];
            S1 += ps[(gid + 8) * 16 + i];
        }
        if (w == 0 && tig == 0) {
            Srow[gid]     = S0;
            Srow[gid + 8] = S1;
        }
        const float t0 = S0 * (1.0f / 2048.0f);
        const float t1 = S1 * (1.0f / 2048.0f);
        #pragma unroll
        for (int nt = 0; nt < 16; nt++) {
            acc[nt][0] = (acc[nt][0] > t0) ? tf32_rna(acc[nt][0]) : 0.f;
            acc[nt][1] = (acc[nt][1] > t0) ? tf32_rna(acc[nt][1]) : 0.f;
            acc[nt][2] = (acc[nt][2] > t1) ? tf32_rna(acc[nt][2]) : 0.f;
            acc[nt][3] = (acc[nt][3] > t1) ? tf32_rna(acc[nt][3]) : 0.f;
        }
    }

    // ---- pass 2: warp w multiplies its register P-slice by V ----
    // shuffle acc (cols 2tig,2tig+1) -> A-frag (cols tig, tig+4) per nt
    {
        float acc2[8][4];
        #pragma unroll
        for (int nt = 0; nt < 8; nt++)
            #pragma unroll
            for (int j = 0; j < 4; j++) acc2[nt][j] = 0.f;

        const int base = lane & ~3;
        const int sl0 = base + (tig >> 1);
        const int sl1 = sl0 + 2;
        const int psel = tig & 1;

        #pragma unroll
        for (int nt = 0; nt < 16; nt++) {
            const float x0 = __shfl_sync(0xffffffffu, acc[nt][0], sl0);
            const float x1 = __shfl_sync(0xffffffffu, acc[nt][1], sl0);
            const float a0 = psel ? x1 : x0;                  // row gid, k tig
            const float y0 = __shfl_sync(0xffffffffu, acc[nt][0], sl1);
            const float y1 = __shfl_sync(0xffffffffu, acc[nt][1], sl1);
            const float a2 = psel ? y1 : y0;                  // row gid, k tig+4
            const float z0 = __shfl_sync(0xffffffffu, acc[nt][2], sl0);
            const float z1 = __shfl_sync(0xffffffffu, acc[nt][3], sl0);
            const float a1 = psel ? z1 : z0;                  // row gid+8, k tig
            const float u0 = __shfl_sync(0xffffffffu, acc[nt][2], sl1);
            const float u1 = __shfl_sync(0xffffffffu, acc[nt][3], sl1);
            const float a3 = psel ? u1 : u0;                  // row gid+8, k tig+4

            const int kb = w * 128 + nt * 8;
            const float* Vr0 = Vb + (size_t)(kb + tig) * DK_ + gid;
            const float* Vr1 = Vb + (size_t)(kb + tig + 4) * DK_ + gid;
            float b0[8], b1[8];
            #pragma unroll
            for (int no = 0; no < 8; no++) {
                b0[no] = Vr0[no * 8];
                b1[no] = Vr1[no * 8];
            }
            #pragma unroll
            for (int no = 0; no < 8; no++)
                mma_k8(acc2[no], a0, a1, a2, a3, b0[no], b1[no]);
        }

        #pragma unroll
        for (int no = 0; no < 8; no++) {
            const int col = no * 8 + tig * 2;
            *(float2*)&redbuf[w * 1024 + gid * 64 + col] =
                make_float2(acc2[no][0], acc2[no][1]);
            *(float2*)&redbuf[w * 1024 + (gid + 8) * 64 + col] =
                make_float2(acc2[no][2], acc2[no][3]);
        }
    }
    __syncthreads();

    // ---- final reduce over 16 warps, divide by S, store ----
    {
        const int o = tid * 2;
        const int r = o >> 6, c = o & 63;
        float s0 = 0.f, s1 = 0.f;
        #pragma unroll
        for (int gg = 0; gg < 16; gg++) {
            const float2 v = *(const float2*)&redbuf[gg * 1024 + o];
            s0 += v.x; s1 += v.y;
        }
        const float inv = 1.0f / Srow[r];
        const int bb = bh >> 3, hh = bh & 7;
        *(float2*)&Og[((size_t)(bb * T_ + row0 + r)) * D_ + hh * 64 + c] =
            make_float2(s0 * inv, s1 * inv);
    }
}

// ---------------------------------------------------------------------------
extern "C" void kernel_launch(void* const* d_in, const int* in_sizes, int n_in,
                              void* d_out, int out_size) {
    const float* q  = (const float*)d_in[0];
    const float* k  = (const float*)d_in[1];
    const float* v  = (const float*)d_in[2];
    const float* Wq = (const float*)d_in[3];
    const float* bq = (const float*)d_in[4];
    const float* Wk = (const float*)d_in[5];
    const float* bk = (const float*)d_in[6];
    const float* Wv = (const float*)d_in[7];
    const float* bv = (const float*)d_in[8];
    const float* Wo = (const float*)d_in[9];
    const float* bo = (const float*)d_in[10];
    float* out = (float*)d_out;

    float *gQ, *gQlo, *gKT, *gV, *gO;
    cudaGetSymbolAddress((void**)&gQ, g_Q);
    cudaGetSymbolAddress((void**)&gQlo, g_Qlo);
    cudaGetSymbolAddress((void**)&gKT, g_KT);
    cudaGetSymbolAddress((void**)&gV, g_V);
    cudaGetSymbolAddress((void**)&gO, g_O);

    cudaFuncSetAttribute(attn_kernel, cudaFuncAttributeMaxDynamicSharedMemorySize,
                         ATTN_SMEM_BYTES);

    tproj_kernel<<<dim3(32, 4, 3), 256>>>(q, k, v, Wq, bq, Wk, bk, Wv, bv,
                                          gQ, gQlo, gKT, gV);
    attn_kernel<<<dim3(128, 16), 512, ATTN_SMEM_BYTES>>>(gQ, gQlo, gKT, gV, gO);
    outproj_kernel<<<dim3(32, 4), 256>>>(gO, Wo, bo, out);
}

// round 13
// speedup vs baseline: 2.9573x; 1.0649x over previous
#include <cuda_runtime.h>
#include <cstdint>

#define B_  2
#define T_  2048
#define D_  512
#define H_  8
#define DK_ 64

__device__ float g_Q  [B_ * H_ * T_ * DK_];   // [bh][t][k] tf32 hi
__device__ float g_Qlo[B_ * H_ * T_ * DK_];   // [bh][t][k] residual
__device__ float g_KT [B_ * H_ * DK_ * T_];   // [bh][k][t] fp32
__device__ float g_V  [B_ * H_ * T_ * DK_];   // [bh][t][k] tf32-rounded
__device__ float g_O  [B_ * T_ * D_];

__device__ __forceinline__ float tf32_rna(float x) {
    uint32_t r;
    asm("cvt.rna.tf32.f32 %0, %1;" : "=r"(r) : "f"(x));
    return __uint_as_float(r);
}
__device__ __forceinline__ void mma_k8(float* d, float a0, float a1, float a2,
                                       float a3, float b0, float b1) {
    asm volatile(
        "mma.sync.aligned.m16n8k8.row.col.f32.tf32.tf32.f32 "
        "{%0,%1,%2,%3}, {%4,%5,%6,%7}, {%8,%9}, {%0,%1,%2,%3};\n"
        : "+f"(d[0]), "+f"(d[1]), "+f"(d[2]), "+f"(d[3])
        : "r"(__float_as_uint(a0)), "r"(__float_as_uint(a1)),
          "r"(__float_as_uint(a2)), "r"(__float_as_uint(a3)),
          "r"(__float_as_uint(b0)), "r"(__float_as_uint(b1)));
}

// ---------------------------------------------------------------------------
// Tensor-core projection GEMM: Y = X@W^T + bias, M=4096, N=K=512.
// 128x128 tile, 256 thr (8 warps, 2m x 4n), warp tile 64x32. 3xTF32 all modes.
// mode 0 (Q): write hi + lo, head layout
// mode 1 (K): write fp32 transposed [bh][k][t]
// mode 2 (V): write tf32-rounded, head layout
// ---------------------------------------------------------------------------
#define KSS 136

__global__ __launch_bounds__(256)
void tproj_kernel(const float* __restrict__ q, const float* __restrict__ k,
                  const float* __restrict__ v,
                  const float* __restrict__ Wq, const float* __restrict__ bq,
                  const float* __restrict__ Wk, const float* __restrict__ bk,
                  const float* __restrict__ Wv, const float* __restrict__ bv,
                  float* __restrict__ gQ, float* __restrict__ gQlo,
                  float* __restrict__ gKT, float* __restrict__ gV) {
    __shared__ float As[32 * KSS];
    __shared__ float Bs[32 * KSS];
    const int mode = blockIdx.z;
    const float* X; const float* W; const float* bias;
    if (mode == 0)      { X = q; W = Wq; bias = bq; }
    else if (mode == 1) { X = k; W = Wk; bias = bk; }
    else                { X = v; W = Wv; bias = bv; }

    const int tid = threadIdx.x;
    const int lane = tid & 31;
    const int gid = lane >> 2, tig = lane & 3;
    const int warp = tid >> 5;
    const int wm = warp >> 2, wn = warp & 3;
    const int m0 = blockIdx.x * 128, n0 = blockIdx.y * 128;

    const int lm  = tid & 127;
    const int lk0 = (tid >> 7) * 2;

    float acc[4][4][4] = {};

    for (int kc = 0; kc < 512; kc += 32) {
        __syncthreads();
        #pragma unroll
        for (int i = 0; i < 4; i++) {
            const int k4 = lk0 + (i & 1) + (i >> 1) * 4;
            const float4 xa = *(const float4*)&X[(size_t)(m0 + lm) * 512 + kc + k4 * 4];
            As[(k4 * 4 + 0) * KSS + lm] = xa.x;
            As[(k4 * 4 + 1) * KSS + lm] = xa.y;
            As[(k4 * 4 + 2) * KSS + lm] = xa.z;
            As[(k4 * 4 + 3) * KSS + lm] = xa.w;
            const float4 wb = *(const float4*)&W[(size_t)(n0 + lm) * 512 + kc + k4 * 4];
            Bs[(k4 * 4 + 0) * KSS + lm] = wb.x;
            Bs[(k4 * 4 + 1) * KSS + lm] = wb.y;
            Bs[(k4 * 4 + 2) * KSS + lm] = wb.z;
            Bs[(k4 * 4 + 3) * KSS + lm] = wb.w;
        }
        __syncthreads();
        #pragma unroll
        for (int ks = 0; ks < 32; ks += 8) {
            float bh0[4], bl0[4], bh1[4], bl1[4];
            #pragma unroll
            for (int nt = 0; nt < 4; nt++) {
                const int n = wn * 32 + nt * 8 + gid;
                const float b0 = Bs[(ks + tig) * KSS + n];
                const float b1 = Bs[(ks + tig + 4) * KSS + n];
                bh0[nt] = tf32_rna(b0); bl0[nt] = b0 - bh0[nt];
                bh1[nt] = tf32_rna(b1); bl1[nt] = b1 - bh1[nt];
            }
            #pragma unroll
            for (int mt = 0; mt < 4; mt++) {
                const int m = wm * 64 + mt * 16 + gid;
                const float a0 = As[(ks + tig) * KSS + m];
                const float a1 = As[(ks + tig) * KSS + m + 8];
                const float a2 = As[(ks + tig + 4) * KSS + m];
                const float a3 = As[(ks + tig + 4) * KSS + m + 8];
                const float a0h = tf32_rna(a0), a0l = a0 - a0h;
                const float a1h = tf32_rna(a1), a1l = a1 - a1h;
                const float a2h = tf32_rna(a2), a2l = a2 - a2h;
                const float a3h = tf32_rna(a3), a3l = a3 - a3h;
                #pragma unroll
                for (int nt = 0; nt < 4; nt++) {
                    mma_k8(acc[mt][nt], a0h, a1h, a2h, a3h, bh0[nt], bh1[nt]);
                    mma_k8(acc[mt][nt], a0h, a1h, a2h, a3h, bl0[nt], bl1[nt]);
                    mma_k8(acc[mt][nt], a0l, a1l, a2l, a3l, bh0[nt], bh1[nt]);
                }
            }
        }
    }

    #pragma unroll
    for (int mt = 0; mt < 4; mt++) {
        #pragma unroll
        for (int nt = 0; nt < 4; nt++) {
            const int mr0 = m0 + wm * 64 + mt * 16 + gid;
            const int mr1 = mr0 + 8;
            const int col = n0 + wn * 32 + nt * 8 + tig * 2;
            const float bs0 = bias[col], bs1 = bias[col + 1];
            const float vals[4] = {acc[mt][nt][0] + bs0, acc[mt][nt][1] + bs1,
                                   acc[mt][nt][2] + bs0, acc[mt][nt][3] + bs1};
            const int rows[2] = {mr0, mr1};
            #pragma unroll
            for (int rr = 0; rr < 2; rr++) {
                const int m = rows[rr];
                const int b = m >> 11, t = m & (T_ - 1);
                #pragma unroll
                for (int cc = 0; cc < 2; cc++) {
                    const int c = col + cc;
                    const int h = c >> 6, d = c & 63;
                    const float val = vals[rr * 2 + cc];
                    if (mode == 1) {
                        gKT[((size_t)((b * H_ + h) * DK_ + d)) * T_ + t] = val;
                    } else {
                        const size_t base =
                            (((size_t)(b * H_ + h)) * T_ + t) * DK_ + d;
                        if (mode == 0) {
                            const float hi = tf32_rna(val);
                            gQ[base] = hi;
                            gQlo[base] = val - hi;
                        } else {
                            gV[base] = tf32_rna(val);
                        }
                    }
                }
            }
        }
    }
}

// ---------------------------------------------------------------------------
// Out-projection: SIMT fp32 GEMM (full precision).
// ---------------------------------------------------------------------------
__global__ __launch_bounds__(256)
void outproj_kernel(const float* __restrict__ X, const float* __restrict__ W,
                    const float* __restrict__ bias, float* __restrict__ Y) {
    __shared__ float Xs[16 * 132];
    __shared__ float Ws[16 * 132];
    const int tid = threadIdx.x;
    const int rg = tid >> 4, cg = tid & 15;
    const int m0 = blockIdx.x * 128, n0 = blockIdx.y * 128;
    const int mm0 = tid >> 2,         kk40 = tid & 3;
    const int mm1 = (tid + 256) >> 2, kk41 = (tid + 256) & 3;

    float acc[8][8] = {};
    float4 xr0, xr1, wr0, wr1;
    xr0 = *(const float4*)&X[(size_t)(m0 + mm0) * 512 + kk40 * 4];
    xr1 = *(const float4*)&X[(size_t)(m0 + mm1) * 512 + kk41 * 4];
    wr0 = *(const float4*)&W[(size_t)(n0 + mm0) * 512 + kk40 * 4];
    wr1 = *(const float4*)&W[(size_t)(n0 + mm1) * 512 + kk41 * 4];

    for (int kt = 0; kt < 512; kt += 16) {
        __syncthreads();
        Xs[(kk40 * 4 + 0) * 132 + mm0] = xr0.x;
        Xs[(kk40 * 4 + 1) * 132 + mm0] = xr0.y;
        Xs[(kk40 * 4 + 2) * 132 + mm0] = xr0.z;
        Xs[(kk40 * 4 + 3) * 132 + mm0] = xr0.w;
        Xs[(kk41 * 4 + 0) * 132 + mm1] = xr1.x;
        Xs[(kk41 * 4 + 1) * 132 + mm1] = xr1.y;
        Xs[(kk41 * 4 + 2) * 132 + mm1] = xr1.z;
        Xs[(kk41 * 4 + 3) * 132 + mm1] = xr1.w;
        Ws[(kk40 * 4 + 0) * 132 + mm0] = wr0.x;
        Ws[(kk40 * 4 + 1) * 132 + mm0] = wr0.y;
        Ws[(kk40 * 4 + 2) * 132 + mm0] = wr0.z;
        Ws[(kk40 * 4 + 3) * 132 + mm0] = wr0.w;
        Ws[(kk41 * 4 + 0) * 132 + mm1] = wr1.x;
        Ws[(kk41 * 4 + 1) * 132 + mm1] = wr1.y;
        Ws[(kk41 * 4 + 2) * 132 + mm1] = wr1.z;
        Ws[(kk41 * 4 + 3) * 132 + mm1] = wr1.w;
        __syncthreads();
        if (kt + 16 < 512) {
            const int kn = kt + 16;
            xr0 = *(const float4*)&X[(size_t)(m0 + mm0) * 512 + kn + kk40 * 4];
            xr1 = *(const float4*)&X[(size_t)(m0 + mm1) * 512 + kn + kk41 * 4];
            wr0 = *(const float4*)&W[(size_t)(n0 + mm0) * 512 + kn + kk40 * 4];
            wr1 = *(const float4*)&W[(size_t)(n0 + mm1) * 512 + kn + kk41 * 4];
        }
        #pragma unroll
        for (int kk = 0; kk < 16; kk++) {
            const float4 a0 = *(const float4*)&Xs[kk * 132 + rg * 4];
            const float4 a1 = *(const float4*)&Xs[kk * 132 + 64 + rg * 4];
            const float4 b0 = *(const float4*)&Ws[kk * 132 + cg * 4];
            const float4 b1 = *(const float4*)&Ws[kk * 132 + 64 + cg * 4];
            const float av[8] = {a0.x, a0.y, a0.z, a0.w, a1.x, a1.y, a1.z, a1.w};
            const float bv[8] = {b0.x, b0.y, b0.z, b0.w, b1.x, b1.y, b1.z, b1.w};
            #pragma unroll
            for (int i = 0; i < 8; i++)
                #pragma unroll
                for (int j = 0; j < 8; j++)
                    acc[i][j] = fmaf(av[i], bv[j], acc[i][j]);
        }
    }

    const float4 bb0 = *(const float4*)&bias[n0 + cg * 4];
    const float4 bb1 = *(const float4*)&bias[n0 + 64 + cg * 4];
    #pragma unroll
    for (int ih = 0; ih < 2; ih++) {
        #pragma unroll
        for (int i = 0; i < 4; i++) {
            const int m = m0 + ih * 64 + rg * 4 + i;
            float4 o0, o1;
            o0.x = acc[ih * 4 + i][0] + bb0.x;
            o0.y = acc[ih * 4 + i][1] + bb0.y;
            o0.z = acc[ih * 4 + i][2] + bb0.z;
            o0.w = acc[ih * 4 + i][3] + bb0.w;
            o1.x = acc[ih * 4 + i][4] + bb1.x;
            o1.y = acc[ih * 4 + i][5] + bb1.y;
            o1.z = acc[ih * 4 + i][6] + bb1.z;
            o1.w = acc[ih * 4 + i][7] + bb1.w;
            *(float4*)&Y[(size_t)m * 512 + n0 + cg * 4] = o0;
            *(float4*)&Y[(size_t)m * 512 + n0 + 64 + cg * 4] = o1;
        }
    }
}

// ---------------------------------------------------------------------------
// Attention: 16 rows/block, 512 threads, 16 warps. P in registers.
// Pass 1 uses m16n8k8 3xTF32 (384 mma/warp vs 768 with k4).
// Smem floats: Qs2 f2[64][17] @0 (2176) | pm @2176 (256) | ps @2432 (256) |
// Srow @2688 (16) | redbuf @2704 (16384)  => 76,352 B
// ---------------------------------------------------------------------------
#define QS_OFF   0
#define PM_OFF   2176
#define PS_OFF   2432
#define SROW_OFF 2688
#define RED_OFF  2704
#define ATTN_SMEM_BYTES ((RED_OFF + 16384) * 4)

__global__ __launch_bounds__(512)
void attn_kernel(const float* __restrict__ Qh, const float* __restrict__ Qlo,
                 const float* __restrict__ KT, const float* __restrict__ Vh,
                 float* __restrict__ Og) {
    extern __shared__ float sm[];
    float2* Qs2    = (float2*)(sm + QS_OFF);   // [k][r] stride 17
    float*  pm     = sm + PM_OFF;              // [row][warp]
    float*  ps     = sm + PS_OFF;
    float*  Srow   = sm + SROW_OFF;
    float*  redbuf = sm + RED_OFF;

    const int tid  = threadIdx.x;
    const int w    = tid >> 5;
    const int lane = tid & 31;
    const int gid  = lane >> 2;     // 0..7
    const int tig  = lane & 3;      // 0..3
    const int bh   = blockIdx.y;
    const int row0 = blockIdx.x * 16;

    const float* Qb  = Qh  + ((size_t)bh * T_ + row0) * DK_;
    const float* Qlb = Qlo + ((size_t)bh * T_ + row0) * DK_;
    const float* KTb = KT  + (size_t)bh * DK_ * T_;
    const float* Vb  = Vh  + (size_t)bh * T_ * DK_;

    if (tid < 256) {
        const int r = tid & 15, k4 = tid >> 4;
        const float4 h4 = *(const float4*)&Qb [(size_t)r * DK_ + k4 * 4];
        const float4 l4 = *(const float4*)&Qlb[(size_t)r * DK_ + k4 * 4];
        Qs2[(k4 * 4 + 0) * 17 + r] = make_float2(h4.x, l4.x);
        Qs2[(k4 * 4 + 1) * 17 + r] = make_float2(h4.y, l4.y);
        Qs2[(k4 * 4 + 2) * 17 + r] = make_float2(h4.z, l4.z);
        Qs2[(k4 * 4 + 3) * 17 + r] = make_float2(h4.w, l4.w);
    }
    __syncthreads();

    // ---- pass 1: 3xTF32 scores via m16n8k8, P into registers ----
    float acc[16][4];
    #pragma unroll
    for (int nt = 0; nt < 16; nt++)
        #pragma unroll
        for (int j = 0; j < 4; j++) acc[nt][j] = 0.f;
    {
        const float* KTl = KTb + (size_t)tig * T_ + w * 128 + gid;
        for (int ksc = 0; ksc < 8; ksc++) {
            // A-frag: rows gid/gid+8, k = ksc*8+tig and +4
            const float2 qa0 = Qs2[(ksc * 8 + tig) * 17 + gid];
            const float2 qa1 = Qs2[(ksc * 8 + tig) * 17 + gid + 8];
            const float2 qb0 = Qs2[(ksc * 8 + tig + 4) * 17 + gid];
            const float2 qb1 = Qs2[(ksc * 8 + tig + 4) * 17 + gid + 8];
            const float* K0 = KTl + (size_t)(ksc * 8) * T_;
            const float* K1 = K0 + (size_t)4 * T_;
            float bk0[16], bk1[16];
            #pragma unroll
            for (int nt = 0; nt < 16; nt++) {
                bk0[nt] = K0[nt * 8];
                bk1[nt] = K1[nt * 8];
            }
            #pragma unroll
            for (int nt = 0; nt < 16; nt++) {
                float* a = acc[nt];
                const float h0 = tf32_rna(bk0[nt]);
                const float l0 = bk0[nt] - h0;
                const float h1 = tf32_rna(bk1[nt]);
                const float l1 = bk1[nt] - h1;
                mma_k8(a, qa0.x, qa1.x, qb0.x, qb1.x, h0, h1);  // qhi·khi
                mma_k8(a, qa0.x, qa1.x, qb0.x, qb1.x, l0, l1);  // qhi·klo
                mma_k8(a, qa0.y, qa1.y, qb0.y, qb1.y, h0, h1);  // qlo·khi
            }
        }
    }

    // ---- row max (in-register + tig-shfl + cross-warp partials) ----
    {
        float m0 = -1e30f, m1 = -1e30f;
        #pragma unroll
        for (int nt = 0; nt < 16; nt++) {
            m0 = fmaxf(m0, fmaxf(acc[nt][0], acc[nt][1]));
            m1 = fmaxf(m1, fmaxf(acc[nt][2], acc[nt][3]));
        }
        m0 = fmaxf(m0, __shfl_xor_sync(0xffffffffu, m0, 1));
        m0 = fmaxf(m0, __shfl_xor_sync(0xffffffffu, m0, 2));
        m1 = fmaxf(m1, __shfl_xor_sync(0xffffffffu, m1, 1));
        m1 = fmaxf(m1, __shfl_xor_sync(0xffffffffu, m1, 2));
        if (tig == 0) {
            pm[gid * 16 + w]       = m0;
            pm[(gid + 8) * 16 + w] = m1;
        }
    }
    __syncthreads();
    float M0 = -1e30f, M1 = -1e30f;
    #pragma unroll
    for (int i = 0; i < 16; i++) {
        M0 = fmaxf(M0, pm[gid * 16 + i]);
        M1 = fmaxf(M1, pm[(gid + 8) * 16 + i]);
    }

    // ---- exp + row sum ----
    {
        float s0 = 0.f, s1 = 0.f;
        #pragma unroll
        for (int nt = 0; nt < 16; nt++) {
            acc[nt][0] = __expf(acc[nt][0] - M0);
            acc[nt][1] = __expf(acc[nt][1] - M0);
            acc[nt][2] = __expf(acc[nt][2] - M1);
            acc[nt][3] = __expf(acc[nt][3] - M1);
            s0 += acc[nt][0] + acc[nt][1];
            s1 += acc[nt][2] + acc[nt][3];
        }
        s0 += __shfl_xor_sync(0xffffffffu, s0, 1);
        s0 += __shfl_xor_sync(0xffffffffu, s0, 2);
        s1 += __shfl_xor_sync(0xffffffffu, s1, 1);
        s1 += __shfl_xor_sync(0xffffffffu, s1, 2);
        if (tig == 0) {
            ps[gid * 16 + w]       = s0;
            ps[(gid + 8) * 16 + w] = s1;
        }
    }
    __syncthreads();
    {
        float S0 = 0.f, S1 = 0.f;
        #pragma unroll
        for (int i = 0; i < 16; i++) {
            S0 += ps[gid * 16 + i];
            S1 += ps[(gid + 8) * 16 + i];
        }
        if (w == 0 && tig == 0) {
            Srow[gid]     = S0;
            Srow[gid + 8] = S1;
        }
        const float t0 = S0 * (1.0f / 2048.0f);
        const float t1 = S1 * (1.0f / 2048.0f);
        #pragma unroll
        for (int nt = 0; nt < 16; nt++) {
            acc[nt][0] = (acc[nt][0] > t0) ? tf32_rna(acc[nt][0]) : 0.f;
            acc[nt][1] = (acc[nt][1] > t0) ? tf32_rna(acc[nt][1]) : 0.f;
            acc[nt][2] = (acc[nt][2] > t1) ? tf32_rna(acc[nt][2]) : 0.f;
            acc[nt][3] = (acc[nt][3] > t1) ? tf32_rna(acc[nt][3]) : 0.f;
        }
    }

    // ---- pass 2: warp w multiplies its register P-slice by V ----
    // V loads issued first (overlap with shuffles), then acc -> A-frag remap
    {
        float acc2[8][4];
        #pragma unroll
        for (int nt = 0; nt < 8; nt++)
            #pragma unroll
            for (int j = 0; j < 4; j++) acc2[nt][j] = 0.f;

        const int base = lane & ~3;
        const int sl0 = base + (tig >> 1);
        const int sl1 = sl0 + 2;
        const int psel = tig & 1;

        #pragma unroll
        for (int nt = 0; nt < 16; nt++) {
            const int kb = w * 128 + nt * 8;
            const float* Vr0 = Vb + (size_t)(kb + tig) * DK_ + gid;
            const float* Vr1 = Vb + (size_t)(kb + tig + 4) * DK_ + gid;
            float b0[8], b1[8];
            #pragma unroll
            for (int no = 0; no < 8; no++) {
                b0[no] = Vr0[no * 8];
                b1[no] = Vr1[no * 8];
            }

            const float x0 = __shfl_sync(0xffffffffu, acc[nt][0], sl0);
            const float x1 = __shfl_sync(0xffffffffu, acc[nt][1], sl0);
            const float a0 = psel ? x1 : x0;                  // row gid, k tig
            const float y0 = __shfl_sync(0xffffffffu, acc[nt][0], sl1);
            const float y1 = __shfl_sync(0xffffffffu, acc[nt][1], sl1);
            const float a2 = psel ? y1 : y0;                  // row gid, k tig+4
            const float z0 = __shfl_sync(0xffffffffu, acc[nt][2], sl0);
            const float z1 = __shfl_sync(0xffffffffu, acc[nt][3], sl0);
            const float a1 = psel ? z1 : z0;                  // row gid+8, k tig
            const float u0 = __shfl_sync(0xffffffffu, acc[nt][2], sl1);
            const float u1 = __shfl_sync(0xffffffffu, acc[nt][3], sl1);
            const float a3 = psel ? u1 : u0;                  // row gid+8, k tig+4

            #pragma unroll
            for (int no = 0; no < 8; no++)
                mma_k8(acc2[no], a0, a1, a2, a3, b0[no], b1[no]);
        }

        #pragma unroll
        for (int no = 0; no < 8; no++) {
            const int col = no * 8 + tig * 2;
            *(float2*)&redbuf[w * 1024 + gid * 64 + col] =
                make_float2(acc2[no][0], acc2[no][1]);
            *(float2*)&redbuf[w * 1024 + (gid + 8) * 64 + col] =
                make_float2(acc2[no][2], acc2[no][3]);
        }
    }
    __syncthreads();

    // ---- final reduce over 16 warps, divide by S, store ----
    {
        const int o = tid * 2;
        const int r = o >> 6, c = o & 63;
        float s0 = 0.f, s1 = 0.f;
        #pragma unroll
        for (int gg = 0; gg < 16; gg++) {
            const float2 v = *(const float2*)&redbuf[gg * 1024 + o];
            s0 += v.x; s1 += v.y;
        }
        const float inv = 1.0f / Srow[r];
        const int bb = bh >> 3, hh = bh & 7;
        *(float2*)&Og[((size_t)(bb * T_ + row0 + r)) * D_ + hh * 64 + c] =
            make_float2(s0 * inv, s1 * inv);
    }
}

// ---------------------------------------------------------------------------
extern "C" void kernel_launch(void* const* d_in, const int* in_sizes, int n_in,
                              void* d_out, int out_size) {
    const float* q  = (const float*)d_in[0];
    const float* k  = (const float*)d_in[1];
    const float* v  = (const float*)d_in[2];
    const float* Wq = (const float*)d_in[3];
    const float* bq = (const float*)d_in[4];
    const float* Wk = (const float*)d_in[5];
    const float* bk = (const float*)d_in[6];
    const float* Wv = (const float*)d_in[7];
    const float* bv = (const float*)d_in[8];
    const float* Wo = (const float*)d_in[9];
    const float* bo = (const float*)d_in[10];
    float* out = (float*)d_out;

    float *gQ, *gQlo, *gKT, *gV, *gO;
    cudaGetSymbolAddress((void**)&gQ, g_Q);
    cudaGetSymbolAddress((void**)&gQlo, g_Qlo);
    cudaGetSymbolAddress((void**)&gKT, g_KT);
    cudaGetSymbolAddress((void**)&gV, g_V);
    cudaGetSymbolAddress((void**)&gO, g_O);

    cudaFuncSetAttribute(attn_kernel, cudaFuncAttributeMaxDynamicSharedMemorySize,
                         ATTN_SMEM_BYTES);

    tproj_kernel<<<dim3(32, 4, 3), 256>>>(q, k, v, Wq, bq, Wk, bk, Wv, bv,
                                          gQ, gQlo, gKT, gV);
    attn_kernel<<<dim3(128, 16), 512, ATTN_SMEM_BYTES>>>(gQ, gQlo, gKT, gV, gO);
    outproj_kernel<<<dim3(32, 4), 256>>>(gO, Wo, bo, out);
}